// round 2
// baseline (speedup 1.0000x reference)
#include <cuda_runtime.h>

#define C_DIM 256
#define L_DIM 1024
#define B_DIM 16
#define NH 8
#define DH 32
#define SCALE 0.17677669529663687f  // 32^-0.5

// Scratch (static device globals -- no allocation at runtime)
__device__ float g_q[B_DIM * C_DIM * L_DIM];
__device__ float g_k[B_DIM * C_DIM * L_DIM];
__device__ float g_v[B_DIM * C_DIM * L_DIM];
__device__ float g_att[B_DIM * C_DIM * L_DIM];

// ---------------------------------------------------------------------------
// Tiled GEMM body: Y[o][l] = (sum_c W[o][c] * X[c][l] + bias[o]) * scale
// O tile = 64 (blockIdx.y), L tile = 64 (blockIdx.x), K tile = 16.
// 256 threads, each computes a 4x4 micro-tile.
// ---------------------------------------------------------------------------
__device__ __forceinline__ void gemm64(const float* __restrict__ W,
                                       const float* __restrict__ bias,
                                       const float* __restrict__ X,
                                       float* __restrict__ Y,
                                       float scale)
{
    __shared__ float As[16][64];  // [k][o] (transposed W tile)
    __shared__ float Bs[16][64];  // [k][l]

    const int tid = threadIdx.x;
    const int tx = tid & 15;      // 0..15 -> l micro
    const int ty = tid >> 4;      // 0..15 -> o micro
    const int o0 = blockIdx.y * 64;
    const int l0 = blockIdx.x * 64;

    // A-tile loader mapping: 64 rows x 16 cols, float4 along k
    const int ar = tid >> 2;          // 0..63 (o within tile)
    const int ac = (tid & 3) * 4;     // 0,4,8,12 (k within tile)
    // B-tile loader mapping: 16 rows x 64 cols, float4 along l
    const int br = tid >> 4;          // 0..15 (k within tile)
    const int bc = (tid & 15) * 4;    // 0..60 (l within tile)

    float acc[4][4] = {};

    for (int k0 = 0; k0 < C_DIM; k0 += 16) {
        float4 a = *(const float4*)&W[(o0 + ar) * C_DIM + k0 + ac];
        float4 b = *(const float4*)&X[(k0 + br) * L_DIM + l0 + bc];
        As[ac + 0][ar] = a.x;
        As[ac + 1][ar] = a.y;
        As[ac + 2][ar] = a.z;
        As[ac + 3][ar] = a.w;
        *(float4*)&Bs[br][bc] = b;
        __syncthreads();

        #pragma unroll
        for (int k = 0; k < 16; k++) {
            float4 av = *(const float4*)&As[k][ty * 4];
            float4 bv = *(const float4*)&Bs[k][tx * 4];
            float aa[4] = {av.x, av.y, av.z, av.w};
            float bb[4] = {bv.x, bv.y, bv.z, bv.w};
            #pragma unroll
            for (int i = 0; i < 4; i++)
                #pragma unroll
                for (int j = 0; j < 4; j++)
                    acc[i][j] += aa[i] * bb[j];
        }
        __syncthreads();
    }

    #pragma unroll
    for (int i = 0; i < 4; i++) {
        int o = o0 + ty * 4 + i;
        float bi = bias[o];
        float4 r;
        r.x = (acc[i][0] + bi) * scale;
        r.y = (acc[i][1] + bi) * scale;
        r.z = (acc[i][2] + bi) * scale;
        r.w = (acc[i][3] + bi) * scale;
        *(float4*)&Y[o * L_DIM + l0 + tx * 4] = r;
    }
}

// Fused Q/K/V projection: grid.z = sel*16 + batch, sel in {0,1,2}
__global__ void __launch_bounds__(256)
proj_qkv_kernel(const float* __restrict__ wq, const float* __restrict__ bq,
                const float* __restrict__ wk, const float* __restrict__ bk,
                const float* __restrict__ wv, const float* __restrict__ bv,
                const float* __restrict__ x)
{
    const int z = blockIdx.z;
    const int b = z & 15;
    const int sel = z >> 4;
    const float* W;
    const float* bi;
    float* Y;
    float sc;
    if (sel == 0)      { W = wq; bi = bq; Y = g_q; sc = SCALE; }
    else if (sel == 1) { W = wk; bi = bk; Y = g_k; sc = 1.0f;  }
    else               { W = wv; bi = bv; Y = g_v; sc = 1.0f;  }
    gemm64(W, bi, x + (size_t)b * C_DIM * L_DIM, Y + (size_t)b * C_DIM * L_DIM, sc);
}

// Output projection: reads g_att, writes final output
__global__ void __launch_bounds__(256)
proj_o_kernel(const float* __restrict__ wo, const float* __restrict__ bo,
              float* __restrict__ out)
{
    const int b = blockIdx.z;
    gemm64(wo, bo, g_att + (size_t)b * C_DIM * L_DIM,
           out + (size_t)b * C_DIM * L_DIM, 1.0f);
}

// ---------------------------------------------------------------------------
// Flash attention: one thread owns one query position l.
// blockIdx.y = (b*8 + head), blockIdx.x = query block of 256.
// K/V tiles of 128 m-positions in smem as float4 along m:
// every LDS.128 feeds 4 FFMAs (broadcast across the warp).
// ---------------------------------------------------------------------------
__global__ void __launch_bounds__(256)
attn_kernel()
{
    const int bn = blockIdx.y;                       // 0..127
    const int l = blockIdx.x * 256 + threadIdx.x;    // query index
    const float* __restrict__ qp = g_q + (size_t)bn * DH * L_DIM;
    const float* __restrict__ kp = g_k + (size_t)bn * DH * L_DIM;
    const float* __restrict__ vp = g_v + (size_t)bn * DH * L_DIM;

    __shared__ float4 ks[DH][32];  // [d][m/4] for a 128-wide m tile
    __shared__ float4 vs[DH][32];

    float q[DH];
    #pragma unroll
    for (int d = 0; d < DH; d++) q[d] = qp[d * L_DIM + l];

    float acc[DH] = {};
    float mmax = -1e30f;
    float lsum = 0.0f;

    for (int m0 = 0; m0 < L_DIM; m0 += 128) {
        __syncthreads();
        #pragma unroll
        for (int i = 0; i < 4; i++) {
            int idx = threadIdx.x + i * 256;   // 0..1023
            int d = idx >> 5;                  // 0..31
            int g = idx & 31;                  // 0..31
            ks[d][g] = *(const float4*)&kp[d * L_DIM + m0 + g * 4];
            vs[d][g] = *(const float4*)&vp[d * L_DIM + m0 + g * 4];
        }
        __syncthreads();

        for (int c = 0; c < 32; c += 4) {      // 16 m-positions per chunk
            float s[16] = {};
            #pragma unroll
            for (int d = 0; d < DH; d++) {
                float qd = q[d];
                float4 kv[4] = {ks[d][c], ks[d][c + 1], ks[d][c + 2], ks[d][c + 3]};
                const float* kf = (const float*)kv;
                #pragma unroll
                for (int j = 0; j < 16; j++) s[j] += qd * kf[j];
            }
            float cm = s[0];
            #pragma unroll
            for (int j = 1; j < 16; j++) cm = fmaxf(cm, s[j]);
            float nm = fmaxf(mmax, cm);
            float corr = __expf(mmax - nm);
            float psum = 0.0f;
            #pragma unroll
            for (int j = 0; j < 16; j++) {
                s[j] = __expf(s[j] - nm);
                psum += s[j];
            }
            lsum = lsum * corr + psum;
            mmax = nm;
            #pragma unroll
            for (int d = 0; d < DH; d++) {
                float a = acc[d] * corr;
                float4 vv[4] = {vs[d][c], vs[d][c + 1], vs[d][c + 2], vs[d][c + 3]};
                const float* vf = (const float*)vv;
                #pragma unroll
                for (int j = 0; j < 16; j++) a += s[j] * vf[j];
                acc[d] = a;
            }
        }
    }

    float inv = 1.0f / lsum;
    float* __restrict__ op = g_att + (size_t)bn * DH * L_DIM;
    #pragma unroll
    for (int d = 0; d < DH; d++) op[d * L_DIM + l] = acc[d] * inv;
}

// ---------------------------------------------------------------------------
extern "C" void kernel_launch(void* const* d_in, const int* in_sizes, int n_in,
                              void* d_out, int out_size)
{
    const float* x  = (const float*)d_in[0];
    const float* wq = (const float*)d_in[1];
    const float* bq = (const float*)d_in[2];
    const float* wk = (const float*)d_in[3];
    const float* bk = (const float*)d_in[4];
    const float* wv = (const float*)d_in[5];
    const float* bv = (const float*)d_in[6];
    const float* wo = (const float*)d_in[7];
    const float* bo = (const float*)d_in[8];
    float* out = (float*)d_out;

    dim3 blk(256);
    proj_qkv_kernel<<<dim3(16, 4, 48), blk>>>(wq, bq, wk, bk, wv, bv, x);
    attn_kernel<<<dim3(4, 128), blk>>>();
    proj_o_kernel<<<dim3(16, 4, 16), blk>>>(wo, bo, out);
}

// round 3
// speedup vs baseline: 1.0843x; 1.0843x over previous
#include <cuda_runtime.h>

#define C_DIM 256
#define L_DIM 1024
#define B_DIM 16
#define NH 8
#define DH 32
#define SCALE 0.17677669529663687f   // 32^-0.5
#define LOG2E 1.4426950408889634f

// Scratch (static device globals -- no allocation at runtime)
__device__ float g_q[B_DIM * C_DIM * L_DIM];
__device__ float g_k[B_DIM * C_DIM * L_DIM];
__device__ float g_v[B_DIM * C_DIM * L_DIM];
__device__ float g_att[B_DIM * C_DIM * L_DIM];

// ---------------- packed f32x2 helpers (Blackwell FFMA2 path) ----------------
typedef unsigned long long ull;

__device__ __forceinline__ ull pack2(float lo, float hi) {
    ull r;
    asm("mov.b64 %0, {%1, %2};" : "=l"(r) : "f"(lo), "f"(hi));
    return r;
}
__device__ __forceinline__ void unpack2(ull v, float& lo, float& hi) {
    asm("mov.b64 {%0, %1}, %2;" : "=f"(lo), "=f"(hi) : "l"(v));
}
__device__ __forceinline__ void ffma2(ull& d, ull a, ull b) {
    asm("fma.rn.f32x2 %0, %1, %2, %0;" : "+l"(d) : "l"(a), "l"(b));
}
__device__ __forceinline__ void fmul2(ull& d, ull a) {
    asm("mul.rn.f32x2 %0, %1, %0;" : "+l"(d) : "l"(a));
}
__device__ __forceinline__ float ex2f(float x) {
    float r;
    asm("ex2.approx.f32 %0, %1;" : "=f"(r) : "f"(x));
    return r;
}

// ---------------------------------------------------------------------------
// Tiled GEMM: Y[o][l] = (sum_c W[o][c] * X[c][l] + bias[o]) * scale
// 128x128 tile, Ktile=16, 256 threads, 8x8 micro-tile via FFMA2.
// ---------------------------------------------------------------------------
__device__ __forceinline__ void gemm128(const float* __restrict__ W,
                                        const float* __restrict__ bias,
                                        const float* __restrict__ X,
                                        float* __restrict__ Y,
                                        float scale)
{
    __shared__ float As[16][132];  // [k][o], padded to keep STS conflicts low
    __shared__ float Bs[16][128];  // [k][l]

    const int tid = threadIdx.x;
    const int tx = tid & 15;       // l micro-group (8 cols)
    const int ty = tid >> 4;       // o micro-group (8 rows)
    const int o0 = blockIdx.y * 128;
    const int l0 = blockIdx.x * 128;

    ull acc2[8][4];
    #pragma unroll
    for (int i = 0; i < 8; i++)
        #pragma unroll
        for (int j = 0; j < 4; j++) acc2[i][j] = 0ull;

    for (int k0 = 0; k0 < C_DIM; k0 += 16) {
        // A tile: 128(o) x 16(k), float4 along k, stored transposed
        #pragma unroll
        for (int i = 0; i < 2; i++) {
            int idx = tid + i * 256;          // 0..511
            int ar = idx >> 2;                // 0..127 (o)
            int ac = (idx & 3) * 4;           // 0,4,8,12 (k)
            float4 a = *(const float4*)&W[(o0 + ar) * C_DIM + k0 + ac];
            As[ac + 0][ar] = a.x;
            As[ac + 1][ar] = a.y;
            As[ac + 2][ar] = a.z;
            As[ac + 3][ar] = a.w;
        }
        // B tile: 16(k) x 128(l), float4 along l
        #pragma unroll
        for (int i = 0; i < 2; i++) {
            int idx = tid + i * 256;
            int br = idx >> 5;                // 0..15 (k)
            int bc = (idx & 31) * 4;          // 0..124 (l)
            *(float4*)&Bs[br][bc] = *(const float4*)&X[(k0 + br) * L_DIM + l0 + bc];
        }
        __syncthreads();

        #pragma unroll
        for (int k = 0; k < 16; k++) {
            float4 a0 = *(const float4*)&As[k][ty * 8];
            float4 a1 = *(const float4*)&As[k][ty * 8 + 4];
            ulonglong2 b0 = *(const ulonglong2*)&Bs[k][tx * 8];
            ulonglong2 b1 = *(const ulonglong2*)&Bs[k][tx * 8 + 4];
            float av[8] = {a0.x, a0.y, a0.z, a0.w, a1.x, a1.y, a1.z, a1.w};
            #pragma unroll
            for (int i = 0; i < 8; i++) {
                ull a2 = pack2(av[i], av[i]);
                ffma2(acc2[i][0], a2, b0.x);
                ffma2(acc2[i][1], a2, b0.y);
                ffma2(acc2[i][2], a2, b1.x);
                ffma2(acc2[i][3], a2, b1.y);
            }
        }
        __syncthreads();
    }

    #pragma unroll
    for (int i = 0; i < 8; i++) {
        int o = o0 + ty * 8 + i;
        float bi = bias[o];
        float r[8];
        #pragma unroll
        for (int j = 0; j < 4; j++) unpack2(acc2[i][j], r[2 * j], r[2 * j + 1]);
        float4 y0, y1;
        y0.x = (r[0] + bi) * scale; y0.y = (r[1] + bi) * scale;
        y0.z = (r[2] + bi) * scale; y0.w = (r[3] + bi) * scale;
        y1.x = (r[4] + bi) * scale; y1.y = (r[5] + bi) * scale;
        y1.z = (r[6] + bi) * scale; y1.w = (r[7] + bi) * scale;
        *(float4*)&Y[o * L_DIM + l0 + tx * 8]     = y0;
        *(float4*)&Y[o * L_DIM + l0 + tx * 8 + 4] = y1;
    }
}

// Fused Q/K/V projection: grid.z = sel*16 + batch
__global__ void __launch_bounds__(256)
proj_qkv_kernel(const float* __restrict__ wq, const float* __restrict__ bq,
                const float* __restrict__ wk, const float* __restrict__ bk,
                const float* __restrict__ wv, const float* __restrict__ bv,
                const float* __restrict__ x)
{
    const int z = blockIdx.z;
    const int b = z & 15;
    const int sel = z >> 4;
    const float* W;
    const float* bi;
    float* Y;
    float sc;
    if (sel == 0)      { W = wq; bi = bq; Y = g_q; sc = SCALE; }
    else if (sel == 1) { W = wk; bi = bk; Y = g_k; sc = 1.0f;  }
    else               { W = wv; bi = bv; Y = g_v; sc = 1.0f;  }
    gemm128(W, bi, x + (size_t)b * C_DIM * L_DIM, Y + (size_t)b * C_DIM * L_DIM, sc);
}

__global__ void __launch_bounds__(256)
proj_o_kernel(const float* __restrict__ wo, const float* __restrict__ bo,
              float* __restrict__ out)
{
    const int b = blockIdx.z;
    gemm128(wo, bo, g_att + (size_t)b * C_DIM * L_DIM,
            out + (size_t)b * C_DIM * L_DIM, 1.0f);
}

// ---------------------------------------------------------------------------
// Flash attention, packed-f32x2 inner loops. One thread = one query.
// ---------------------------------------------------------------------------
__global__ void __launch_bounds__(256)
attn_kernel()
{
    const int bn = blockIdx.y;                       // (b*8 + head)
    const int l = blockIdx.x * 256 + threadIdx.x;    // query index
    const float* __restrict__ qp = g_q + (size_t)bn * DH * L_DIM;
    const float* __restrict__ kp = g_k + (size_t)bn * DH * L_DIM;
    const float* __restrict__ vp = g_v + (size_t)bn * DH * L_DIM;

    __shared__ float4 ks[DH][32];  // [d][m/4], 128-wide m tile
    __shared__ float4 vs[DH][32];

    // q pre-scaled by log2e so softmax exp is a single ex2
    ull q2[DH];
    #pragma unroll
    for (int d = 0; d < DH; d++) {
        float qd = qp[d * L_DIM + l] * LOG2E;
        q2[d] = pack2(qd, qd);
    }

    ull acc2[DH];
    #pragma unroll
    for (int d = 0; d < DH; d++) acc2[d] = 0ull;
    float mmax = -1e30f;
    float lsum = 0.0f;

    for (int m0 = 0; m0 < L_DIM; m0 += 128) {
        __syncthreads();
        #pragma unroll
        for (int i = 0; i < 4; i++) {
            int idx = threadIdx.x + i * 256;   // 0..1023
            int d = idx >> 5;
            int g = idx & 31;
            ks[d][g] = *(const float4*)&kp[d * L_DIM + m0 + g * 4];
            vs[d][g] = *(const float4*)&vp[d * L_DIM + m0 + g * 4];
        }
        __syncthreads();

        for (int c = 0; c < 32; c += 4) {      // 16 m-positions per chunk
            // ---- QK: s (in log2 units), packed over m-pairs ----
            ull s2[8];
            #pragma unroll
            for (int j = 0; j < 8; j++) s2[j] = 0ull;
            #pragma unroll
            for (int d = 0; d < DH; d++) {
                ull qd = q2[d];
                ulonglong2 u0 = *(const ulonglong2*)&ks[d][c];
                ulonglong2 u1 = *(const ulonglong2*)&ks[d][c + 1];
                ulonglong2 u2 = *(const ulonglong2*)&ks[d][c + 2];
                ulonglong2 u3 = *(const ulonglong2*)&ks[d][c + 3];
                ffma2(s2[0], qd, u0.x); ffma2(s2[1], qd, u0.y);
                ffma2(s2[2], qd, u1.x); ffma2(s2[3], qd, u1.y);
                ffma2(s2[4], qd, u2.x); ffma2(s2[5], qd, u2.y);
                ffma2(s2[6], qd, u3.x); ffma2(s2[7], qd, u3.y);
            }
            float s[16];
            #pragma unroll
            for (int j = 0; j < 8; j++) unpack2(s2[j], s[2 * j], s[2 * j + 1]);

            // ---- online softmax (base-2) ----
            float cm = s[0];
            #pragma unroll
            for (int j = 1; j < 16; j++) cm = fmaxf(cm, s[j]);
            if (cm > mmax) {
                float corr = ex2f(mmax - cm);
                lsum *= corr;
                ull corr2 = pack2(corr, corr);
                #pragma unroll
                for (int d = 0; d < DH; d++) fmul2(acc2[d], corr2);
                mmax = cm;
            }
            float psum = 0.0f;
            #pragma unroll
            for (int j = 0; j < 16; j++) {
                s[j] = ex2f(s[j] - mmax);
                psum += s[j];
            }
            lsum += psum;
            ull p2[8];
            #pragma unroll
            for (int j = 0; j < 8; j++) p2[j] = pack2(s[2 * j], s[2 * j + 1]);

            // ---- AV: packed over m-pairs, per-d accumulators ----
            #pragma unroll
            for (int d = 0; d < DH; d++) {
                ulonglong2 u0 = *(const ulonglong2*)&vs[d][c];
                ulonglong2 u1 = *(const ulonglong2*)&vs[d][c + 1];
                ulonglong2 u2 = *(const ulonglong2*)&vs[d][c + 2];
                ulonglong2 u3 = *(const ulonglong2*)&vs[d][c + 3];
                ull a = acc2[d];
                ffma2(a, p2[0], u0.x); ffma2(a, p2[1], u0.y);
                ffma2(a, p2[2], u1.x); ffma2(a, p2[3], u1.y);
                ffma2(a, p2[4], u2.x); ffma2(a, p2[5], u2.y);
                ffma2(a, p2[6], u3.x); ffma2(a, p2[7], u3.y);
                acc2[d] = a;
            }
        }
    }

    float inv = 1.0f / lsum;
    float* __restrict__ op = g_att + (size_t)bn * DH * L_DIM;
    #pragma unroll
    for (int d = 0; d < DH; d++) {
        float lo, hi;
        unpack2(acc2[d], lo, hi);
        op[d * L_DIM + l] = (lo + hi) * inv;
    }
}

// ---------------------------------------------------------------------------
extern "C" void kernel_launch(void* const* d_in, const int* in_sizes, int n_in,
                              void* d_out, int out_size)
{
    const float* x  = (const float*)d_in[0];
    const float* wq = (const float*)d_in[1];
    const float* bq = (const float*)d_in[2];
    const float* wk = (const float*)d_in[3];
    const float* bk = (const float*)d_in[4];
    const float* wv = (const float*)d_in[5];
    const float* bv = (const float*)d_in[6];
    const float* wo = (const float*)d_in[7];
    const float* bo = (const float*)d_in[8];
    float* out = (float*)d_out;

    dim3 blk(256);
    proj_qkv_kernel<<<dim3(8, 2, 48), blk>>>(wq, bq, wk, bk, wv, bv, x);
    attn_kernel<<<dim3(4, 128), blk>>>();
    proj_o_kernel<<<dim3(8, 2, 16), blk>>>(wo, bo, out);
}

// round 4
// speedup vs baseline: 1.0850x; 1.0006x over previous
#include <cuda_runtime.h>

#define C_DIM 256
#define L_DIM 1024
#define B_DIM 16
#define NH 8
#define DH 32
#define SCALE 0.17677669529663687f   // 32^-0.5
#define LOG2E 1.4426950408889634f

// Scratch (static device globals -- no allocation at runtime)
__device__ float g_q[B_DIM * C_DIM * L_DIM];
__device__ float g_k[B_DIM * C_DIM * L_DIM];
__device__ float g_v[B_DIM * C_DIM * L_DIM];
__device__ float g_att[B_DIM * C_DIM * L_DIM];

// ---------------- packed f32x2 helpers (Blackwell FFMA2 path) ----------------
typedef unsigned long long ull;

__device__ __forceinline__ ull pack2(float lo, float hi) {
    ull r;
    asm("mov.b64 %0, {%1, %2};" : "=l"(r) : "f"(lo), "f"(hi));
    return r;
}
__device__ __forceinline__ void unpack2(ull v, float& lo, float& hi) {
    asm("mov.b64 {%0, %1}, %2;" : "=f"(lo), "=f"(hi) : "l"(v));
}
__device__ __forceinline__ void ffma2(ull& d, ull a, ull b) {
    asm("fma.rn.f32x2 %0, %1, %2, %0;" : "+l"(d) : "l"(a), "l"(b));
}
__device__ __forceinline__ void fmul2(ull& d, ull a) {
    asm("mul.rn.f32x2 %0, %1, %0;" : "+l"(d) : "l"(a));
}
__device__ __forceinline__ float ex2f(float x) {
    float r;
    asm("ex2.approx.f32 %0, %1;" : "=f"(r) : "f"(x));
    return r;
}

// ---------------------------------------------------------------------------
// Tiled GEMM: Y[o][l] = (sum_c W[o][c] * X[c][l] + bias[o]) * scale
// 128x128 tile, Ktile=16, 256 threads, 8x8 micro-tile via FFMA2.
// ---------------------------------------------------------------------------
__device__ __forceinline__ void gemm128(const float* __restrict__ W,
                                        const float* __restrict__ bias,
                                        const float* __restrict__ X,
                                        float* __restrict__ Y,
                                        float scale)
{
    __shared__ float As[16][132];  // [k][o], padded to keep STS conflicts low
    __shared__ float Bs[16][128];  // [k][l]

    const int tid = threadIdx.x;
    const int tx = tid & 15;       // l micro-group (8 cols)
    const int ty = tid >> 4;       // o micro-group (8 rows)
    const int o0 = blockIdx.y * 128;
    const int l0 = blockIdx.x * 128;

    ull acc2[8][4];
    #pragma unroll
    for (int i = 0; i < 8; i++)
        #pragma unroll
        for (int j = 0; j < 4; j++) acc2[i][j] = 0ull;

    for (int k0 = 0; k0 < C_DIM; k0 += 16) {
        // A tile: 128(o) x 16(k), float4 along k, stored transposed
        #pragma unroll
        for (int i = 0; i < 2; i++) {
            int idx = tid + i * 256;          // 0..511
            int ar = idx >> 2;                // 0..127 (o)
            int ac = (idx & 3) * 4;           // 0,4,8,12 (k)
            float4 a = *(const float4*)&W[(o0 + ar) * C_DIM + k0 + ac];
            As[ac + 0][ar] = a.x;
            As[ac + 1][ar] = a.y;
            As[ac + 2][ar] = a.z;
            As[ac + 3][ar] = a.w;
        }
        // B tile: 16(k) x 128(l), float4 along l
        #pragma unroll
        for (int i = 0; i < 2; i++) {
            int idx = tid + i * 256;
            int br = idx >> 5;                // 0..15 (k)
            int bc = (idx & 31) * 4;          // 0..124 (l)
            *(float4*)&Bs[br][bc] = *(const float4*)&X[(k0 + br) * L_DIM + l0 + bc];
        }
        __syncthreads();

        #pragma unroll
        for (int k = 0; k < 16; k++) {
            float4 a0 = *(const float4*)&As[k][ty * 8];
            float4 a1 = *(const float4*)&As[k][ty * 8 + 4];
            ulonglong2 b0 = *(const ulonglong2*)&Bs[k][tx * 8];
            ulonglong2 b1 = *(const ulonglong2*)&Bs[k][tx * 8 + 4];
            float av[8] = {a0.x, a0.y, a0.z, a0.w, a1.x, a1.y, a1.z, a1.w};
            #pragma unroll
            for (int i = 0; i < 8; i++) {
                ull a2 = pack2(av[i], av[i]);
                ffma2(acc2[i][0], a2, b0.x);
                ffma2(acc2[i][1], a2, b0.y);
                ffma2(acc2[i][2], a2, b1.x);
                ffma2(acc2[i][3], a2, b1.y);
            }
        }
        __syncthreads();
    }

    #pragma unroll
    for (int i = 0; i < 8; i++) {
        int o = o0 + ty * 8 + i;
        float bi = bias[o];
        float r[8];
        #pragma unroll
        for (int j = 0; j < 4; j++) unpack2(acc2[i][j], r[2 * j], r[2 * j + 1]);
        float4 y0, y1;
        y0.x = (r[0] + bi) * scale; y0.y = (r[1] + bi) * scale;
        y0.z = (r[2] + bi) * scale; y0.w = (r[3] + bi) * scale;
        y1.x = (r[4] + bi) * scale; y1.y = (r[5] + bi) * scale;
        y1.z = (r[6] + bi) * scale; y1.w = (r[7] + bi) * scale;
        *(float4*)&Y[o * L_DIM + l0 + tx * 8]     = y0;
        *(float4*)&Y[o * L_DIM + l0 + tx * 8 + 4] = y1;
    }
}

// Fused Q/K/V projection: grid.z = sel*16 + batch
__global__ void __launch_bounds__(256)
proj_qkv_kernel(const float* __restrict__ wq, const float* __restrict__ bq,
                const float* __restrict__ wk, const float* __restrict__ bk,
                const float* __restrict__ wv, const float* __restrict__ bv,
                const float* __restrict__ x)
{
    const int z = blockIdx.z;
    const int b = z & 15;
    const int sel = z >> 4;
    const float* W;
    const float* bi;
    float* Y;
    float sc;
    if (sel == 0)      { W = wq; bi = bq; Y = g_q; sc = SCALE; }
    else if (sel == 1) { W = wk; bi = bk; Y = g_k; sc = 1.0f;  }
    else               { W = wv; bi = bv; Y = g_v; sc = 1.0f;  }
    gemm128(W, bi, x + (size_t)b * C_DIM * L_DIM, Y + (size_t)b * C_DIM * L_DIM, sc);
}

__global__ void __launch_bounds__(256)
proj_o_kernel(const float* __restrict__ wo, const float* __restrict__ bo,
              float* __restrict__ out)
{
    const int b = blockIdx.z;
    gemm128(wo, bo, g_att + (size_t)b * C_DIM * L_DIM,
            out + (size_t)b * C_DIM * L_DIM, 1.0f);
}

// ---------------------------------------------------------------------------
// Flash attention, packed-f32x2 inner loops. One thread = one query.
// ---------------------------------------------------------------------------
__global__ void __launch_bounds__(256)
attn_kernel()
{
    const int bn = blockIdx.y;                       // (b*8 + head)
    const int l = blockIdx.x * 256 + threadIdx.x;    // query index
    const float* __restrict__ qp = g_q + (size_t)bn * DH * L_DIM;
    const float* __restrict__ kp = g_k + (size_t)bn * DH * L_DIM;
    const float* __restrict__ vp = g_v + (size_t)bn * DH * L_DIM;

    __shared__ float4 ks[DH][32];  // [d][m/4], 128-wide m tile
    __shared__ float4 vs[DH][32];

    // q pre-scaled by log2e so softmax exp is a single ex2
    ull q2[DH];
    #pragma unroll
    for (int d = 0; d < DH; d++) {
        float qd = qp[d * L_DIM + l] * LOG2E;
        q2[d] = pack2(qd, qd);
    }

    ull acc2[DH];
    #pragma unroll
    for (int d = 0; d < DH; d++) acc2[d] = 0ull;
    float mmax = -1e30f;
    float lsum = 0.0f;

    for (int m0 = 0; m0 < L_DIM; m0 += 128) {
        __syncthreads();
        #pragma unroll
        for (int i = 0; i < 4; i++) {
            int idx = threadIdx.x + i * 256;   // 0..1023
            int d = idx >> 5;
            int g = idx & 31;
            ks[d][g] = *(const float4*)&kp[d * L_DIM + m0 + g * 4];
            vs[d][g] = *(const float4*)&vp[d * L_DIM + m0 + g * 4];
        }
        __syncthreads();

        for (int c = 0; c < 32; c += 4) {      // 16 m-positions per chunk
            // ---- QK: s (in log2 units), packed over m-pairs ----
            ull s2[8];
            #pragma unroll
            for (int j = 0; j < 8; j++) s2[j] = 0ull;
            #pragma unroll
            for (int d = 0; d < DH; d++) {
                ull qd = q2[d];
                ulonglong2 u0 = *(const ulonglong2*)&ks[d][c];
                ulonglong2 u1 = *(const ulonglong2*)&ks[d][c + 1];
                ulonglong2 u2 = *(const ulonglong2*)&ks[d][c + 2];
                ulonglong2 u3 = *(const ulonglong2*)&ks[d][c + 3];
                ffma2(s2[0], qd, u0.x); ffma2(s2[1], qd, u0.y);
                ffma2(s2[2], qd, u1.x); ffma2(s2[3], qd, u1.y);
                ffma2(s2[4], qd, u2.x); ffma2(s2[5], qd, u2.y);
                ffma2(s2[6], qd, u3.x); ffma2(s2[7], qd, u3.y);
            }
            float s[16];
            #pragma unroll
            for (int j = 0; j < 8; j++) unpack2(s2[j], s[2 * j], s[2 * j + 1]);

            // ---- online softmax (base-2) ----
            float cm = s[0];
            #pragma unroll
            for (int j = 1; j < 16; j++) cm = fmaxf(cm, s[j]);
            if (cm > mmax) {
                float corr = ex2f(mmax - cm);
                lsum *= corr;
                ull corr2 = pack2(corr, corr);
                #pragma unroll
                for (int d = 0; d < DH; d++) fmul2(acc2[d], corr2);
                mmax = cm;
            }
            float psum = 0.0f;
            #pragma unroll
            for (int j = 0; j < 16; j++) {
                s[j] = ex2f(s[j] - mmax);
                psum += s[j];
            }
            lsum += psum;
            ull p2[8];
            #pragma unroll
            for (int j = 0; j < 8; j++) p2[j] = pack2(s[2 * j], s[2 * j + 1]);

            // ---- AV: packed over m-pairs, per-d accumulators ----
            #pragma unroll
            for (int d = 0; d < DH; d++) {
                ulonglong2 u0 = *(const ulonglong2*)&vs[d][c];
                ulonglong2 u1 = *(const ulonglong2*)&vs[d][c + 1];
                ulonglong2 u2 = *(const ulonglong2*)&vs[d][c + 2];
                ulonglong2 u3 = *(const ulonglong2*)&vs[d][c + 3];
                ull a = acc2[d];
                ffma2(a, p2[0], u0.x); ffma2(a, p2[1], u0.y);
                ffma2(a, p2[2], u1.x); ffma2(a, p2[3], u1.y);
                ffma2(a, p2[4], u2.x); ffma2(a, p2[5], u2.y);
                ffma2(a, p2[6], u3.x); ffma2(a, p2[7], u3.y);
                acc2[d] = a;
            }
        }
    }

    float inv = 1.0f / lsum;
    float* __restrict__ op = g_att + (size_t)bn * DH * L_DIM;
    #pragma unroll
    for (int d = 0; d < DH; d++) {
        float lo, hi;
        unpack2(acc2[d], lo, hi);
        op[d * L_DIM + l] = (lo + hi) * inv;
    }
}

// ---------------------------------------------------------------------------
extern "C" void kernel_launch(void* const* d_in, const int* in_sizes, int n_in,
                              void* d_out, int out_size)
{
    const float* x  = (const float*)d_in[0];
    const float* wq = (const float*)d_in[1];
    const float* bq = (const float*)d_in[2];
    const float* wk = (const float*)d_in[3];
    const float* bk = (const float*)d_in[4];
    const float* wv = (const float*)d_in[5];
    const float* bv = (const float*)d_in[6];
    const float* wo = (const float*)d_in[7];
    const float* bo = (const float*)d_in[8];
    float* out = (float*)d_out;

    dim3 blk(256);
    proj_qkv_kernel<<<dim3(8, 2, 48), blk>>>(wq, bq, wk, bk, wv, bv, x);
    attn_kernel<<<dim3(4, 128), blk>>>();
    proj_o_kernel<<<dim3(8, 2, 16), blk>>>(wo, bo, out);
}

// round 6
// speedup vs baseline: 1.8049x; 1.6636x over previous
#include <cuda_runtime.h>
#include <cuda_fp16.h>
#include <cstdint>

#define C_DIM 256
#define L_DIM 1024
#define B_DIM 16
#define NH 8
#define DH 32
#define SCALE 0.17677669529663687f
#define LOG2E 1.4426950408889634f

__device__ float g_q[B_DIM * C_DIM * L_DIM];   // [b][c][l], scaled by SCALE*LOG2E
__device__ float g_k[B_DIM * C_DIM * L_DIM];
__device__ float g_v[B_DIM * C_DIM * L_DIM];
__device__ float g_att[B_DIM * C_DIM * L_DIM];
__device__ __half g_qh[B_DIM * L_DIM * C_DIM];   // [b][l][c]
__device__ __half g_ql[B_DIM * L_DIM * C_DIM];
__device__ __half g_kh2[B_DIM * C_DIM * L_DIM]; // [b][c][l]
__device__ __half g_kl2[B_DIM * C_DIM * L_DIM];
__device__ __half g_vth[B_DIM * L_DIM * C_DIM]; // [b][l][c]
__device__ __half g_vtl[B_DIM * L_DIM * C_DIM];

typedef unsigned long long ull;
__device__ __forceinline__ ull pack2(float lo, float hi) {
    ull r; asm("mov.b64 %0, {%1, %2};" : "=l"(r) : "f"(lo), "f"(hi)); return r;
}
__device__ __forceinline__ void unpack2(ull v, float& lo, float& hi) {
    asm("mov.b64 {%0, %1}, %2;" : "=f"(lo), "=f"(hi) : "l"(v));
}
__device__ __forceinline__ void ffma2(ull& d, ull a, ull b) {
    asm("fma.rn.f32x2 %0, %1, %2, %0;" : "+l"(d) : "l"(a), "l"(b));
}
__device__ __forceinline__ float ex2f(float x) {
    float r; asm("ex2.approx.f32 %0, %1;" : "=f"(r) : "f"(x)); return r;
}
__device__ __forceinline__ uint32_t smem_u32(const void* p) {
    uint32_t a;
    asm("{ .reg .u64 t; cvta.to.shared.u64 t, %1; cvt.u32.u64 %0, t; }" : "=r"(a) : "l"(p));
    return a;
}
__device__ __forceinline__ uint32_t pack_h2(float lo, float hi) {
    uint32_t r; asm("cvt.rn.f16x2.f32 %0, %1, %2;" : "=r"(r) : "f"(hi), "f"(lo)); return r;
}
__device__ __forceinline__ void ldsm_x4(uint32_t* r, uint32_t a) {
    asm volatile("ldmatrix.sync.aligned.m8n8.x4.shared.b16 {%0,%1,%2,%3}, [%4];"
        : "=r"(r[0]), "=r"(r[1]), "=r"(r[2]), "=r"(r[3]) : "r"(a));
}
__device__ __forceinline__ void ldsm_x2t(uint32_t* r, uint32_t a) {
    asm volatile("ldmatrix.sync.aligned.m8n8.x2.trans.shared.b16 {%0,%1}, [%2];"
        : "=r"(r[0]), "=r"(r[1]) : "r"(a));
}
__device__ __forceinline__ void mma16816(float* d, const uint32_t* a, const uint32_t* b) {
    asm volatile("mma.sync.aligned.m16n8k16.row.col.f32.f16.f16.f32 "
        "{%0,%1,%2,%3}, {%4,%5,%6,%7}, {%8,%9}, {%0,%1,%2,%3};"
        : "+f"(d[0]), "+f"(d[1]), "+f"(d[2]), "+f"(d[3])
        : "r"(a[0]), "r"(a[1]), "r"(a[2]), "r"(a[3]), "r"(b[0]), "r"(b[1]));
}
__device__ __forceinline__ float shflx(float v, int m) {
    return __shfl_xor_sync(0xffffffffu, v, m);
}

// ------------------- scalar projection GEMM (measured-good) -------------------
__device__ __forceinline__ void gemm128(const float* __restrict__ W, const float* __restrict__ bias,
                                        const float* __restrict__ X, float* __restrict__ Y, float scale)
{
    __shared__ float As[16][132];
    __shared__ float Bs[16][128];
    const int tid = threadIdx.x, tx = tid & 15, ty = tid >> 4;
    const int o0 = blockIdx.y * 128, l0 = blockIdx.x * 128;
    ull acc2[8][4];
    #pragma unroll
    for (int i = 0; i < 8; i++)
        #pragma unroll
        for (int j = 0; j < 4; j++) acc2[i][j] = 0ull;
    for (int k0 = 0; k0 < C_DIM; k0 += 16) {
        #pragma unroll
        for (int i = 0; i < 2; i++) {
            int idx = tid + i * 256, ar = idx >> 2, ac = (idx & 3) * 4;
            float4 a = *(const float4*)&W[(o0 + ar) * C_DIM + k0 + ac];
            As[ac + 0][ar] = a.x; As[ac + 1][ar] = a.y; As[ac + 2][ar] = a.z; As[ac + 3][ar] = a.w;
        }
        #pragma unroll
        for (int i = 0; i < 2; i++) {
            int idx = tid + i * 256, br = idx >> 5, bc = (idx & 31) * 4;
            *(float4*)&Bs[br][bc] = *(const float4*)&X[(k0 + br) * L_DIM + l0 + bc];
        }
        __syncthreads();
        #pragma unroll
        for (int k = 0; k < 16; k++) {
            float4 a0 = *(const float4*)&As[k][ty * 8];
            float4 a1 = *(const float4*)&As[k][ty * 8 + 4];
            ulonglong2 b0 = *(const ulonglong2*)&Bs[k][tx * 8];
            ulonglong2 b1 = *(const ulonglong2*)&Bs[k][tx * 8 + 4];
            float av[8] = {a0.x, a0.y, a0.z, a0.w, a1.x, a1.y, a1.z, a1.w};
            #pragma unroll
            for (int i = 0; i < 8; i++) {
                ull a2 = pack2(av[i], av[i]);
                ffma2(acc2[i][0], a2, b0.x); ffma2(acc2[i][1], a2, b0.y);
                ffma2(acc2[i][2], a2, b1.x); ffma2(acc2[i][3], a2, b1.y);
            }
        }
        __syncthreads();
    }
    #pragma unroll
    for (int i = 0; i < 8; i++) {
        int o = o0 + ty * 8 + i;
        float bi = bias[o], r[8];
        #pragma unroll
        for (int j = 0; j < 4; j++) unpack2(acc2[i][j], r[2 * j], r[2 * j + 1]);
        float4 y0, y1;
        y0.x = (r[0] + bi) * scale; y0.y = (r[1] + bi) * scale;
        y0.z = (r[2] + bi) * scale; y0.w = (r[3] + bi) * scale;
        y1.x = (r[4] + bi) * scale; y1.y = (r[5] + bi) * scale;
        y1.z = (r[6] + bi) * scale; y1.w = (r[7] + bi) * scale;
        *(float4*)&Y[o * L_DIM + l0 + tx * 8] = y0;
        *(float4*)&Y[o * L_DIM + l0 + tx * 8 + 4] = y1;
    }
}

__global__ void __launch_bounds__(256)
proj_qkv_kernel(const float* __restrict__ wq, const float* __restrict__ bq,
                const float* __restrict__ wk, const float* __restrict__ bk,
                const float* __restrict__ wv, const float* __restrict__ bv,
                const float* __restrict__ x)
{
    const int z = blockIdx.z, b = z & 15, sel = z >> 4;
    const float* W; const float* bi; float* Y; float sc;
    if (sel == 0)      { W = wq; bi = bq; Y = g_q; sc = SCALE * LOG2E; }
    else if (sel == 1) { W = wk; bi = bk; Y = g_k; sc = 1.0f; }
    else               { W = wv; bi = bv; Y = g_v; sc = 1.0f; }
    gemm128(W, bi, x + (size_t)b * C_DIM * L_DIM, Y + (size_t)b * C_DIM * L_DIM, sc);
}

__global__ void __launch_bounds__(256)
proj_o_kernel(const float* __restrict__ wo, const float* __restrict__ bo, float* __restrict__ out)
{
    const int b = blockIdx.z;
    gemm128(wo, bo, g_att + (size_t)b * C_DIM * L_DIM, out + (size_t)b * C_DIM * L_DIM, 1.0f);
}

// ------------------- conversions: fp32 -> f16 hi/lo -------------------
// transpose-split: [b][c][l] -> [b][l][c].  sel 0 = q, 1 = v
__global__ void __launch_bounds__(256)
convert_t_kernel()
{
    __shared__ float tile[32][33];
    const int sel = blockIdx.z & 1, b = blockIdx.z >> 1;
    const float* src = (sel ? g_v : g_q) + (size_t)b * C_DIM * L_DIM;
    __half* dh = (sel ? g_vth : g_qh) + (size_t)b * L_DIM * C_DIM;
    __half* dl = (sel ? g_vtl : g_ql) + (size_t)b * L_DIM * C_DIM;
    const int l0 = blockIdx.x * 32, c0 = blockIdx.y * 32;
    const int tx = threadIdx.x, ty = threadIdx.y;
    #pragma unroll
    for (int i = 0; i < 4; i++)
        tile[ty + 8 * i][tx] = src[(size_t)(c0 + ty + 8 * i) * L_DIM + l0 + tx];
    __syncthreads();
    #pragma unroll
    for (int i = 0; i < 4; i++) {
        float v = tile[tx][ty + 8 * i];
        __half h = __float2half_rn(v);
        size_t o = (size_t)(l0 + ty + 8 * i) * C_DIM + c0 + tx;
        dh[o] = h;
        dl[o] = __float2half_rn(v - __half2float(h));
    }
}

// elementwise split: k stays [b][c][l]
__global__ void __launch_bounds__(256)
convert_k_kernel()
{
    int i = blockIdx.x * 256 + threadIdx.x;
    const float2 v = ((const float2*)g_k)[i];
    __half2 h = __floats2half2_rn(v.x, v.y);
    float2 hf = __half22float2(h);
    ((__half2*)g_kh2)[i] = h;
    ((__half2*)g_kl2)[i] = __floats2half2_rn(v.x - hf.x, v.y - hf.y);
}

// ------------------- mma.sync flash attention -------------------
// CTA: (qt, head, b); 8 warps x 16 queries; key tiles of 64.
__global__ void __launch_bounds__(256, 1)
attn_mma_kernel()
{
    __shared__ __align__(16) __half qsh[2][128 * 40];  // [h/l][query][c], pitch 40
    __shared__ __align__(16) __half ksh[2][32 * 72];   // [h/l][c][key],  pitch 72
    __shared__ __align__(16) __half vsh[2][64 * 40];   // [h/l][key][d],  pitch 40

    const int tid = threadIdx.x, lane = tid & 31, w = tid >> 5;
    const int qt = blockIdx.x, n = blockIdx.y, b = blockIdx.z;

    // stage Q (128 rows x 32 halves)
    for (int u = tid; u < 512; u += 256) {
        int row = u >> 2, seg = u & 3;
        size_t g = ((size_t)(b * 1024 + qt * 128 + row)) * C_DIM + n * 32 + seg * 8;
        *(uint4*)&qsh[0][row * 40 + seg * 8] = *(const uint4*)&g_qh[g];
        *(uint4*)&qsh[1][row * 40 + seg * 8] = *(const uint4*)&g_ql[g];
    }
    __syncthreads();

    // Q fragments: [h/l][kchunk][4]
    uint32_t qf[2][2][4];
    {
        int r = lane & 15;
        int chi = (lane & 16) ? 8 : 0;
        #pragma unroll
        for (int hl = 0; hl < 2; hl++)
            #pragma unroll
            for (int kc = 0; kc < 2; kc++)
                ldsm_x4(qf[hl][kc], smem_u32(&qsh[hl][(w * 16 + r) * 40 + kc * 16 + chi]));
    }

    float oacc[4][4] = {};
    float m0 = -1e30f, m1 = -1e30f, l0 = 0.0f, l1 = 0.0f;
    const int rr = lane & 15;

    for (int t = 0; t < 16; t++) {
        __syncthreads();
        {
            int row = tid >> 3, seg = tid & 7;        // K: 32 rows x 8 segs
            size_t g = ((size_t)(b * 256 + n * 32 + row)) * L_DIM + t * 64 + seg * 8;
            *(uint4*)&ksh[0][row * 72 + seg * 8] = *(const uint4*)&g_kh2[g];
            *(uint4*)&ksh[1][row * 72 + seg * 8] = *(const uint4*)&g_kl2[g];
            int vrow = tid >> 2, vseg = tid & 3;      // V: 64 rows x 4 segs
            size_t gv = ((size_t)(b * 1024 + t * 64 + vrow)) * C_DIM + n * 32 + vseg * 8;
            *(uint4*)&vsh[0][vrow * 40 + vseg * 8] = *(const uint4*)&g_vth[gv];
            *(uint4*)&vsh[1][vrow * 40 + vseg * 8] = *(const uint4*)&g_vtl[gv];
        }
        __syncthreads();

        // ---- S = QhKh + QhKl + QlKh : 8 ntiles (8 keys each) ----
        float sacc[8][4];
        #pragma unroll
        for (int nt = 0; nt < 8; nt++) {
            sacc[nt][0] = sacc[nt][1] = sacc[nt][2] = sacc[nt][3] = 0.0f;
            uint32_t kbh[2][2], kbl[2][2];
            #pragma unroll
            for (int kc = 0; kc < 2; kc++) {
                ldsm_x2t(kbh[kc], smem_u32(&ksh[0][(kc * 16 + rr) * 72 + nt * 8]));
                ldsm_x2t(kbl[kc], smem_u32(&ksh[1][(kc * 16 + rr) * 72 + nt * 8]));
            }
            #pragma unroll
            for (int kc = 0; kc < 2; kc++) {
                mma16816(sacc[nt], qf[0][kc], kbh[kc]);
                mma16816(sacc[nt], qf[0][kc], kbl[kc]);
                mma16816(sacc[nt], qf[1][kc], kbh[kc]);
            }
        }

        // ---- online softmax (base-2 logits) ----
        float mt0 = -1e30f, mt1 = -1e30f;
        #pragma unroll
        for (int nt = 0; nt < 8; nt++) {
            mt0 = fmaxf(mt0, fmaxf(sacc[nt][0], sacc[nt][1]));
            mt1 = fmaxf(mt1, fmaxf(sacc[nt][2], sacc[nt][3]));
        }
        mt0 = fmaxf(mt0, shflx(mt0, 1)); mt0 = fmaxf(mt0, shflx(mt0, 2));
        mt1 = fmaxf(mt1, shflx(mt1, 1)); mt1 = fmaxf(mt1, shflx(mt1, 2));
        float nm0 = fmaxf(m0, mt0), nm1 = fmaxf(m1, mt1);
        float c0 = ex2f(m0 - nm0), c1 = ex2f(m1 - nm1);
        m0 = nm0; m1 = nm1;
        l0 *= c0; l1 *= c1;
        #pragma unroll
        for (int nt = 0; nt < 4; nt++) {
            oacc[nt][0] *= c0; oacc[nt][1] *= c0;
            oacc[nt][2] *= c1; oacc[nt][3] *= c1;
        }
        float rs0 = 0.0f, rs1 = 0.0f;
        #pragma unroll
        for (int nt = 0; nt < 8; nt++) {
            sacc[nt][0] = ex2f(sacc[nt][0] - m0);
            sacc[nt][1] = ex2f(sacc[nt][1] - m0);
            sacc[nt][2] = ex2f(sacc[nt][2] - m1);
            sacc[nt][3] = ex2f(sacc[nt][3] - m1);
            rs0 += sacc[nt][0] + sacc[nt][1];
            rs1 += sacc[nt][2] + sacc[nt][3];
        }
        rs0 += shflx(rs0, 1); rs0 += shflx(rs0, 2);
        rs1 += shflx(rs1, 1); rs1 += shflx(rs1, 2);
        l0 += rs0; l1 += rs1;

        // ---- pack P into A fragments (hi + residual) ----
        uint32_t pfh[4][4], pfl[4][4];
        #pragma unroll
        for (int kc = 0; kc < 4; kc++) {
            const float* s0 = sacc[2 * kc];
            const float* s1 = sacc[2 * kc + 1];
            pfh[kc][0] = pack_h2(s0[0], s0[1]);
            pfh[kc][1] = pack_h2(s0[2], s0[3]);
            pfh[kc][2] = pack_h2(s1[0], s1[1]);
            pfh[kc][3] = pack_h2(s1[2], s1[3]);
            float2 f0 = __half22float2(*(__half2*)&pfh[kc][0]);
            float2 f1 = __half22float2(*(__half2*)&pfh[kc][1]);
            float2 f2 = __half22float2(*(__half2*)&pfh[kc][2]);
            float2 f3 = __half22float2(*(__half2*)&pfh[kc][3]);
            pfl[kc][0] = pack_h2(s0[0] - f0.x, s0[1] - f0.y);
            pfl[kc][1] = pack_h2(s0[2] - f1.x, s0[3] - f1.y);
            pfl[kc][2] = pack_h2(s1[0] - f2.x, s1[1] - f2.y);
            pfl[kc][3] = pack_h2(s1[2] - f3.x, s1[3] - f3.y);
        }

        // ---- O += PhVh + PhVl + PlVh : 4 d-tiles x 4 k-chunks ----
        #pragma unroll
        for (int nt = 0; nt < 4; nt++) {
            #pragma unroll
            for (int kc = 0; kc < 4; kc++) {
                uint32_t vbh[2], vbl[2];
                ldsm_x2t(vbh, smem_u32(&vsh[0][(kc * 16 + rr) * 40 + nt * 8]));
                ldsm_x2t(vbl, smem_u32(&vsh[1][(kc * 16 + rr) * 40 + nt * 8]));
                mma16816(oacc[nt], pfh[kc], vbh);
                mma16816(oacc[nt], pfh[kc], vbl);
                mma16816(oacc[nt], pfl[kc], vbh);
            }
        }
    }

    // ---- epilogue ----
    float i0 = 1.0f / l0, i1 = 1.0f / l1;
    int q0 = qt * 128 + w * 16 + (lane >> 2);
    #pragma unroll
    for (int nt = 0; nt < 4; nt++) {
        size_t base = ((size_t)(b * 256 + n * 32 + nt * 8 + (lane & 3) * 2)) * L_DIM + q0;
        g_att[base] = oacc[nt][0] * i0;
        g_att[base + L_DIM] = oacc[nt][1] * i0;
        g_att[base + 8] = oacc[nt][2] * i1;
        g_att[base + L_DIM + 8] = oacc[nt][3] * i1;
    }
}

// ---------------------------------------------------------------------------
extern "C" void kernel_launch(void* const* d_in, const int* in_sizes, int n_in,
                              void* d_out, int out_size)
{
    const float* x  = (const float*)d_in[0];
    const float* wq = (const float*)d_in[1];
    const float* bq = (const float*)d_in[2];
    const float* wk = (const float*)d_in[3];
    const float* bk = (const float*)d_in[4];
    const float* wv = (const float*)d_in[5];
    const float* bv = (const float*)d_in[6];
    const float* wo = (const float*)d_in[7];
    const float* bo = (const float*)d_in[8];
    float* out = (float*)d_out;

    proj_qkv_kernel<<<dim3(8, 2, 48), 256>>>(wq, bq, wk, bk, wv, bv, x);
    convert_t_kernel<<<dim3(32, 8, 32), dim3(32, 8)>>>();
    convert_k_kernel<<<8192, 256>>>();
    attn_mma_kernel<<<dim3(8, 8, 16), 256>>>();
    proj_o_kernel<<<dim3(8, 2, 16), 256>>>(wo, bo, out);
}

// round 7
// speedup vs baseline: 2.1870x; 1.2117x over previous
#include <cuda_runtime.h>
#include <cuda_fp16.h>
#include <cstdint>

#define C_DIM 256
#define L_DIM 1024
#define B_DIM 16
#define NH 8
#define DH 32
#define SCALE 0.17677669529663687f
#define LOG2E 1.4426950408889634f

__device__ float g_q[B_DIM * L_DIM * C_DIM];   // [b][l][c] after mma projection
__device__ float g_k[B_DIM * L_DIM * C_DIM];   // [b][l][c]
__device__ float g_v[B_DIM * L_DIM * C_DIM];   // [b][l][c]
__device__ float g_att[B_DIM * C_DIM * L_DIM]; // [b][c][l]
__device__ __half g_qh[B_DIM * L_DIM * C_DIM];   // [b][l][c]
__device__ __half g_ql[B_DIM * L_DIM * C_DIM];
__device__ __half g_kh2[B_DIM * C_DIM * L_DIM];  // [b][c][l]
__device__ __half g_kl2[B_DIM * C_DIM * L_DIM];
__device__ __half g_vth[B_DIM * L_DIM * C_DIM];  // [b][l][c]
__device__ __half g_vtl[B_DIM * L_DIM * C_DIM];
__device__ __half g_xth[B_DIM * L_DIM * C_DIM];  // x^T [b][l][c]
__device__ __half g_xtl[B_DIM * L_DIM * C_DIM];
__device__ __half g_wh[3 * C_DIM * C_DIM];       // W^T [sel][c][o]
__device__ __half g_wl[3 * C_DIM * C_DIM];

typedef unsigned long long ull;
__device__ __forceinline__ ull pack2(float lo, float hi) {
    ull r; asm("mov.b64 %0, {%1, %2};" : "=l"(r) : "f"(lo), "f"(hi)); return r;
}
__device__ __forceinline__ void unpack2(ull v, float& lo, float& hi) {
    asm("mov.b64 {%0, %1}, %2;" : "=f"(lo), "=f"(hi) : "l"(v));
}
__device__ __forceinline__ void ffma2(ull& d, ull a, ull b) {
    asm("fma.rn.f32x2 %0, %1, %2, %0;" : "+l"(d) : "l"(a), "l"(b));
}
__device__ __forceinline__ float ex2f(float x) {
    float r; asm("ex2.approx.f32 %0, %1;" : "=f"(r) : "f"(x)); return r;
}
__device__ __forceinline__ uint32_t smem_u32(const void* p) {
    uint32_t a;
    asm("{ .reg .u64 t; cvta.to.shared.u64 t, %1; cvt.u32.u64 %0, t; }" : "=r"(a) : "l"(p));
    return a;
}
__device__ __forceinline__ uint32_t pack_h2(float lo, float hi) {
    uint32_t r; asm("cvt.rn.f16x2.f32 %0, %1, %2;" : "=r"(r) : "f"(hi), "f"(lo)); return r;
}
__device__ __forceinline__ void ldsm_x4(uint32_t* r, uint32_t a) {
    asm volatile("ldmatrix.sync.aligned.m8n8.x4.shared.b16 {%0,%1,%2,%3}, [%4];"
        : "=r"(r[0]), "=r"(r[1]), "=r"(r[2]), "=r"(r[3]) : "r"(a));
}
__device__ __forceinline__ void ldsm_x2t(uint32_t* r, uint32_t a) {
    asm volatile("ldmatrix.sync.aligned.m8n8.x2.trans.shared.b16 {%0,%1}, [%2];"
        : "=r"(r[0]), "=r"(r[1]) : "r"(a));
}
__device__ __forceinline__ void mma16816(float* d, const uint32_t* a, const uint32_t* b) {
    asm volatile("mma.sync.aligned.m16n8k16.row.col.f32.f16.f16.f32 "
        "{%0,%1,%2,%3}, {%4,%5,%6,%7}, {%8,%9}, {%0,%1,%2,%3};"
        : "+f"(d[0]), "+f"(d[1]), "+f"(d[2]), "+f"(d[3])
        : "r"(a[0]), "r"(a[1]), "r"(a[2]), "r"(a[3]), "r"(b[0]), "r"(b[1]));
}
__device__ __forceinline__ float shflx(float v, int m) {
    return __shfl_xor_sync(0xffffffffu, v, m);
}

// ------------------- scalar GEMM (kept for proj_o) -------------------
__device__ __forceinline__ void gemm128(const float* __restrict__ W, const float* __restrict__ bias,
                                        const float* __restrict__ X, float* __restrict__ Y, float scale)
{
    __shared__ float As[16][132];
    __shared__ float Bs[16][128];
    const int tid = threadIdx.x, tx = tid & 15, ty = tid >> 4;
    const int o0 = blockIdx.y * 128, l0 = blockIdx.x * 128;
    ull acc2[8][4];
    #pragma unroll
    for (int i = 0; i < 8; i++)
        #pragma unroll
        for (int j = 0; j < 4; j++) acc2[i][j] = 0ull;
    for (int k0 = 0; k0 < C_DIM; k0 += 16) {
        #pragma unroll
        for (int i = 0; i < 2; i++) {
            int idx = tid + i * 256, ar = idx >> 2, ac = (idx & 3) * 4;
            float4 a = *(const float4*)&W[(o0 + ar) * C_DIM + k0 + ac];
            As[ac + 0][ar] = a.x; As[ac + 1][ar] = a.y; As[ac + 2][ar] = a.z; As[ac + 3][ar] = a.w;
        }
        #pragma unroll
        for (int i = 0; i < 2; i++) {
            int idx = tid + i * 256, br = idx >> 5, bc = (idx & 31) * 4;
            *(float4*)&Bs[br][bc] = *(const float4*)&X[(k0 + br) * L_DIM + l0 + bc];
        }
        __syncthreads();
        #pragma unroll
        for (int k = 0; k < 16; k++) {
            float4 a0 = *(const float4*)&As[k][ty * 8];
            float4 a1 = *(const float4*)&As[k][ty * 8 + 4];
            ulonglong2 b0 = *(const ulonglong2*)&Bs[k][tx * 8];
            ulonglong2 b1 = *(const ulonglong2*)&Bs[k][tx * 8 + 4];
            float av[8] = {a0.x, a0.y, a0.z, a0.w, a1.x, a1.y, a1.z, a1.w};
            #pragma unroll
            for (int i = 0; i < 8; i++) {
                ull a2 = pack2(av[i], av[i]);
                ffma2(acc2[i][0], a2, b0.x); ffma2(acc2[i][1], a2, b0.y);
                ffma2(acc2[i][2], a2, b1.x); ffma2(acc2[i][3], a2, b1.y);
            }
        }
        __syncthreads();
    }
    #pragma unroll
    for (int i = 0; i < 8; i++) {
        int o = o0 + ty * 8 + i;
        float bi = bias[o], r[8];
        #pragma unroll
        for (int j = 0; j < 4; j++) unpack2(acc2[i][j], r[2 * j], r[2 * j + 1]);
        float4 y0, y1;
        y0.x = (r[0] + bi) * scale; y0.y = (r[1] + bi) * scale;
        y0.z = (r[2] + bi) * scale; y0.w = (r[3] + bi) * scale;
        y1.x = (r[4] + bi) * scale; y1.y = (r[5] + bi) * scale;
        y1.z = (r[6] + bi) * scale; y1.w = (r[7] + bi) * scale;
        *(float4*)&Y[o * L_DIM + l0 + tx * 8] = y0;
        *(float4*)&Y[o * L_DIM + l0 + tx * 8 + 4] = y1;
    }
}

__global__ void __launch_bounds__(256)
proj_o_kernel(const float* __restrict__ wo, const float* __restrict__ bo, float* __restrict__ out)
{
    const int b = blockIdx.z;
    gemm128(wo, bo, g_att + (size_t)b * C_DIM * L_DIM, out + (size_t)b * C_DIM * L_DIM, 1.0f);
}

// ------------------- prep: W^T split, x^T split -------------------
__global__ void __launch_bounds__(256)
split_w_kernel(const float* __restrict__ wq, const float* __restrict__ wk, const float* __restrict__ wv)
{
    __shared__ float t[32][33];
    const int sel = blockIdx.z;
    const float* W = (sel == 0) ? wq : (sel == 1) ? wk : wv;
    __half* dh = g_wh + sel * C_DIM * C_DIM;
    __half* dl = g_wl + sel * C_DIM * C_DIM;
    const int o0 = blockIdx.x * 32, c0 = blockIdx.y * 32;
    const int tx = threadIdx.x, ty = threadIdx.y;
    #pragma unroll
    for (int i = 0; i < 4; i++)
        t[ty + 8 * i][tx] = W[(o0 + ty + 8 * i) * C_DIM + c0 + tx];
    __syncthreads();
    #pragma unroll
    for (int i = 0; i < 4; i++) {
        float v = t[tx][ty + 8 * i];                 // W[o0+tx][c0+ty+8i]
        __half h = __float2half_rn(v);
        int o = (c0 + ty + 8 * i) * C_DIM + o0 + tx; // [c][o]
        dh[o] = h;
        dl[o] = __float2half_rn(v - __half2float(h));
    }
}

__global__ void __launch_bounds__(256)
convert_x_kernel(const float* __restrict__ x)
{
    __shared__ float t[32][33];
    const int b = blockIdx.z;
    const float* src = x + (size_t)b * C_DIM * L_DIM;       // [c][l]
    __half* dh = g_xth + (size_t)b * L_DIM * C_DIM;          // [l][c]
    __half* dl = g_xtl + (size_t)b * L_DIM * C_DIM;
    const int l0 = blockIdx.x * 32, c0 = blockIdx.y * 32;
    const int tx = threadIdx.x, ty = threadIdx.y;
    #pragma unroll
    for (int i = 0; i < 4; i++)
        t[ty + 8 * i][tx] = src[(size_t)(c0 + ty + 8 * i) * L_DIM + l0 + tx];
    __syncthreads();
    #pragma unroll
    for (int i = 0; i < 4; i++) {
        float v = t[tx][ty + 8 * i];
        __half h = __float2half_rn(v);
        size_t o = (size_t)(l0 + ty + 8 * i) * C_DIM + c0 + tx;
        dh[o] = h;
        dl[o] = __float2half_rn(v - __half2float(h));
    }
}

// ------------------- mma.sync QKV projection -------------------
// CTA: 128(l) x 128(o) tile. grid.x = ltile*2 + ohalf, grid.y = sel, grid.z = b.
__global__ void __launch_bounds__(256)
proj_qkv_mma_kernel(const float* __restrict__ bq, const float* __restrict__ bk,
                    const float* __restrict__ bv)
{
    __shared__ __align__(16) __half ash[2][128 * 40];   // [hl][l][c-chunk 32] pitch 40
    __shared__ __align__(16) __half bsh[2][32 * 136];   // [hl][c][o 128] pitch 136
    __shared__ float bias_s[128];

    const int tid = threadIdx.x, lane = tid & 31, w = tid >> 5;
    const int lt = blockIdx.x >> 1, oh = blockIdx.x & 1;
    const int sel = blockIdx.y, b = blockIdx.z;

    const __half* xh = g_xth + (size_t)b * L_DIM * C_DIM;
    const __half* xl = g_xtl + (size_t)b * L_DIM * C_DIM;
    const __half* wh = g_wh + sel * C_DIM * C_DIM;
    const __half* wl = g_wl + sel * C_DIM * C_DIM;
    const float* bias = (sel == 0) ? bq : (sel == 1) ? bk : bv;
    float* Y = (sel == 0) ? g_q : (sel == 1) ? g_k : g_v;
    const float sc = (sel == 0) ? (SCALE * LOG2E) : 1.0f;

    if (tid < 128) bias_s[tid] = bias[oh * 128 + tid];

    float acc[16][4] = {};
    const int rr = lane & 15;
    const int chi = (lane & 16) ? 8 : 0;

    for (int kc0 = 0; kc0 < C_DIM; kc0 += 32) {
        __syncthreads();
        // A: 128 l-rows x 32 c
        #pragma unroll
        for (int i = 0; i < 2; i++) {
            int u = tid + i * 256;               // 0..511
            int row = u >> 2, seg = u & 3;
            size_t g = (size_t)(lt * 128 + row) * C_DIM + kc0 + seg * 8;
            *(uint4*)&ash[0][row * 40 + seg * 8] = *(const uint4*)&xh[g];
            *(uint4*)&ash[1][row * 40 + seg * 8] = *(const uint4*)&xl[g];
        }
        // B: 32 c-rows x 128 o
        #pragma unroll
        for (int i = 0; i < 2; i++) {
            int u = tid + i * 256;
            int row = u >> 4, seg = u & 15;
            int g = (kc0 + row) * C_DIM + oh * 128 + seg * 8;
            *(uint4*)&bsh[0][row * 136 + seg * 8] = *(const uint4*)&wh[g];
            *(uint4*)&bsh[1][row * 136 + seg * 8] = *(const uint4*)&wl[g];
        }
        __syncthreads();

        uint32_t af[2][2][4];
        #pragma unroll
        for (int hl = 0; hl < 2; hl++)
            #pragma unroll
            for (int kc = 0; kc < 2; kc++)
                ldsm_x4(af[hl][kc], smem_u32(&ash[hl][(w * 16 + rr) * 40 + kc * 16 + chi]));

        #pragma unroll
        for (int nt = 0; nt < 16; nt++) {
            #pragma unroll
            for (int kc = 0; kc < 2; kc++) {
                uint32_t bh[2], bl[2];
                ldsm_x2t(bh, smem_u32(&bsh[0][(kc * 16 + rr) * 136 + nt * 8]));
                ldsm_x2t(bl, smem_u32(&bsh[1][(kc * 16 + rr) * 136 + nt * 8]));
                mma16816(acc[nt], af[0][kc], bh);
                mma16816(acc[nt], af[0][kc], bl);
                mma16816(acc[nt], af[1][kc], bh);
            }
        }
    }

    // epilogue: Y [b][l][o], coalesced float2 stores
    const int r0 = lt * 128 + w * 16 + (lane >> 2);
    #pragma unroll
    for (int nt = 0; nt < 16; nt++) {
        int c0 = nt * 8 + (lane & 3) * 2;
        float b0 = bias_s[c0], b1 = bias_s[c0 + 1];
        float2 y0, y1;
        y0.x = (acc[nt][0] + b0) * sc; y0.y = (acc[nt][1] + b1) * sc;
        y1.x = (acc[nt][2] + b0) * sc; y1.y = (acc[nt][3] + b1) * sc;
        *(float2*)&Y[((size_t)(b * 1024 + r0)) * C_DIM + oh * 128 + c0] = y0;
        *(float2*)&Y[((size_t)(b * 1024 + r0 + 8)) * C_DIM + oh * 128 + c0] = y1;
    }
}

// ------------------- converts from [b][l][c] fp32 -------------------
__global__ void __launch_bounds__(256)
convert_qv_kernel()
{
    const int sel = blockIdx.y;
    int i = blockIdx.x * 256 + threadIdx.x;
    const float2 v = ((const float2*)(sel ? g_v : g_q))[i];
    __half2 h = __floats2half2_rn(v.x, v.y);
    float2 hf = __half22float2(h);
    ((__half2*)(sel ? g_vth : g_qh))[i] = h;
    ((__half2*)(sel ? g_vtl : g_ql))[i] = __floats2half2_rn(v.x - hf.x, v.y - hf.y);
}

__global__ void __launch_bounds__(256)
convert_k_t_kernel()   // g_k [b][l][c] -> g_kh2/g_kl2 [b][c][l]
{
    __shared__ float t[32][33];
    const int b = blockIdx.z;
    const float* src = g_k + (size_t)b * L_DIM * C_DIM;
    __half* dh = g_kh2 + (size_t)b * C_DIM * L_DIM;
    __half* dl = g_kl2 + (size_t)b * C_DIM * L_DIM;
    const int l0 = blockIdx.x * 32, c0 = blockIdx.y * 32;
    const int tx = threadIdx.x, ty = threadIdx.y;
    #pragma unroll
    for (int i = 0; i < 4; i++)
        t[ty + 8 * i][tx] = src[(size_t)(l0 + ty + 8 * i) * C_DIM + c0 + tx];
    __syncthreads();
    #pragma unroll
    for (int i = 0; i < 4; i++) {
        float v = t[tx][ty + 8 * i];                 // src[l0+tx][c0+ty+8i]
        __half h = __float2half_rn(v);
        size_t o = (size_t)(c0 + ty + 8 * i) * L_DIM + l0 + tx;
        dh[o] = h;
        dl[o] = __float2half_rn(v - __half2float(h));
    }
}

// ------------------- mma.sync flash attention (unchanged from R6) -------------------
__global__ void __launch_bounds__(256, 1)
attn_mma_kernel()
{
    __shared__ __align__(16) __half qsh[2][128 * 40];
    __shared__ __align__(16) __half ksh[2][32 * 72];
    __shared__ __align__(16) __half vsh[2][64 * 40];

    const int tid = threadIdx.x, lane = tid & 31, w = tid >> 5;
    const int qt = blockIdx.x, n = blockIdx.y, b = blockIdx.z;

    for (int u = tid; u < 512; u += 256) {
        int row = u >> 2, seg = u & 3;
        size_t g = ((size_t)(b * 1024 + qt * 128 + row)) * C_DIM + n * 32 + seg * 8;
        *(uint4*)&qsh[0][row * 40 + seg * 8] = *(const uint4*)&g_qh[g];
        *(uint4*)&qsh[1][row * 40 + seg * 8] = *(const uint4*)&g_ql[g];
    }
    __syncthreads();

    uint32_t qf[2][2][4];
    {
        int r = lane & 15;
        int chi = (lane & 16) ? 8 : 0;
        #pragma unroll
        for (int hl = 0; hl < 2; hl++)
            #pragma unroll
            for (int kc = 0; kc < 2; kc++)
                ldsm_x4(qf[hl][kc], smem_u32(&qsh[hl][(w * 16 + r) * 40 + kc * 16 + chi]));
    }

    float oacc[4][4] = {};
    float m0 = -1e30f, m1 = -1e30f, l0 = 0.0f, l1 = 0.0f;
    const int rr = lane & 15;

    for (int t = 0; t < 16; t++) {
        __syncthreads();
        {
            int row = tid >> 3, seg = tid & 7;
            size_t g = ((size_t)(b * 256 + n * 32 + row)) * L_DIM + t * 64 + seg * 8;
            *(uint4*)&ksh[0][row * 72 + seg * 8] = *(const uint4*)&g_kh2[g];
            *(uint4*)&ksh[1][row * 72 + seg * 8] = *(const uint4*)&g_kl2[g];
            int vrow = tid >> 2, vseg = tid & 3;
            size_t gv = ((size_t)(b * 1024 + t * 64 + vrow)) * C_DIM + n * 32 + vseg * 8;
            *(uint4*)&vsh[0][vrow * 40 + vseg * 8] = *(const uint4*)&g_vth[gv];
            *(uint4*)&vsh[1][vrow * 40 + vseg * 8] = *(const uint4*)&g_vtl[gv];
        }
        __syncthreads();

        float sacc[8][4];
        #pragma unroll
        for (int nt = 0; nt < 8; nt++) {
            sacc[nt][0] = sacc[nt][1] = sacc[nt][2] = sacc[nt][3] = 0.0f;
            uint32_t kbh[2][2], kbl[2][2];
            #pragma unroll
            for (int kc = 0; kc < 2; kc++) {
                ldsm_x2t(kbh[kc], smem_u32(&ksh[0][(kc * 16 + rr) * 72 + nt * 8]));
                ldsm_x2t(kbl[kc], smem_u32(&ksh[1][(kc * 16 + rr) * 72 + nt * 8]));
            }
            #pragma unroll
            for (int kc = 0; kc < 2; kc++) {
                mma16816(sacc[nt], qf[0][kc], kbh[kc]);
                mma16816(sacc[nt], qf[0][kc], kbl[kc]);
                mma16816(sacc[nt], qf[1][kc], kbh[kc]);
            }
        }

        float mt0 = -1e30f, mt1 = -1e30f;
        #pragma unroll
        for (int nt = 0; nt < 8; nt++) {
            mt0 = fmaxf(mt0, fmaxf(sacc[nt][0], sacc[nt][1]));
            mt1 = fmaxf(mt1, fmaxf(sacc[nt][2], sacc[nt][3]));
        }
        mt0 = fmaxf(mt0, shflx(mt0, 1)); mt0 = fmaxf(mt0, shflx(mt0, 2));
        mt1 = fmaxf(mt1, shflx(mt1, 1)); mt1 = fmaxf(mt1, shflx(mt1, 2));
        float nm0 = fmaxf(m0, mt0), nm1 = fmaxf(m1, mt1);
        float c0 = ex2f(m0 - nm0), c1 = ex2f(m1 - nm1);
        m0 = nm0; m1 = nm1;
        l0 *= c0; l1 *= c1;
        #pragma unroll
        for (int nt = 0; nt < 4; nt++) {
            oacc[nt][0] *= c0; oacc[nt][1] *= c0;
            oacc[nt][2] *= c1; oacc[nt][3] *= c1;
        }
        float rs0 = 0.0f, rs1 = 0.0f;
        #pragma unroll
        for (int nt = 0; nt < 8; nt++) {
            sacc[nt][0] = ex2f(sacc[nt][0] - m0);
            sacc[nt][1] = ex2f(sacc[nt][1] - m0);
            sacc[nt][2] = ex2f(sacc[nt][2] - m1);
            sacc[nt][3] = ex2f(sacc[nt][3] - m1);
            rs0 += sacc[nt][0] + sacc[nt][1];
            rs1 += sacc[nt][2] + sacc[nt][3];
        }
        rs0 += shflx(rs0, 1); rs0 += shflx(rs0, 2);
        rs1 += shflx(rs1, 1); rs1 += shflx(rs1, 2);
        l0 += rs0; l1 += rs1;

        uint32_t pfh[4][4], pfl[4][4];
        #pragma unroll
        for (int kc = 0; kc < 4; kc++) {
            const float* s0 = sacc[2 * kc];
            const float* s1 = sacc[2 * kc + 1];
            pfh[kc][0] = pack_h2(s0[0], s0[1]);
            pfh[kc][1] = pack_h2(s0[2], s0[3]);
            pfh[kc][2] = pack_h2(s1[0], s1[1]);
            pfh[kc][3] = pack_h2(s1[2], s1[3]);
            float2 f0 = __half22float2(*(__half2*)&pfh[kc][0]);
            float2 f1 = __half22float2(*(__half2*)&pfh[kc][1]);
            float2 f2 = __half22float2(*(__half2*)&pfh[kc][2]);
            float2 f3 = __half22float2(*(__half2*)&pfh[kc][3]);
            pfl[kc][0] = pack_h2(s0[0] - f0.x, s0[1] - f0.y);
            pfl[kc][1] = pack_h2(s0[2] - f1.x, s0[3] - f1.y);
            pfl[kc][2] = pack_h2(s1[0] - f2.x, s1[1] - f2.y);
            pfl[kc][3] = pack_h2(s1[2] - f3.x, s1[3] - f3.y);
        }

        #pragma unroll
        for (int nt = 0; nt < 4; nt++) {
            #pragma unroll
            for (int kc = 0; kc < 4; kc++) {
                uint32_t vbh[2], vbl[2];
                ldsm_x2t(vbh, smem_u32(&vsh[0][(kc * 16 + rr) * 40 + nt * 8]));
                ldsm_x2t(vbl, smem_u32(&vsh[1][(kc * 16 + rr) * 40 + nt * 8]));
                mma16816(oacc[nt], pfh[kc], vbh);
                mma16816(oacc[nt], pfh[kc], vbl);
                mma16816(oacc[nt], pfl[kc], vbh);
            }
        }
    }

    float i0 = 1.0f / l0, i1 = 1.0f / l1;
    int q0 = qt * 128 + w * 16 + (lane >> 2);
    #pragma unroll
    for (int nt = 0; nt < 4; nt++) {
        size_t base = ((size_t)(b * 256 + n * 32 + nt * 8 + (lane & 3) * 2)) * L_DIM + q0;
        g_att[base] = oacc[nt][0] * i0;
        g_att[base + L_DIM] = oacc[nt][1] * i0;
        g_att[base + 8] = oacc[nt][2] * i1;
        g_att[base + L_DIM + 8] = oacc[nt][3] * i1;
    }
}

// ---------------------------------------------------------------------------
extern "C" void kernel_launch(void* const* d_in, const int* in_sizes, int n_in,
                              void* d_out, int out_size)
{
    const float* x  = (const float*)d_in[0];
    const float* wq = (const float*)d_in[1];
    const float* bq = (const float*)d_in[2];
    const float* wk = (const float*)d_in[3];
    const float* bk = (const float*)d_in[4];
    const float* wv = (const float*)d_in[5];
    const float* bv = (const float*)d_in[6];
    const float* wo = (const float*)d_in[7];
    const float* bo = (const float*)d_in[8];
    float* out = (float*)d_out;

    split_w_kernel<<<dim3(8, 8, 3), dim3(32, 8)>>>(wq, wk, wv);
    convert_x_kernel<<<dim3(32, 8, 16), dim3(32, 8)>>>(x);
    proj_qkv_mma_kernel<<<dim3(16, 3, 16), 256>>>(bq, bk, bv);
    convert_qv_kernel<<<dim3(8192, 2), 256>>>();
    convert_k_t_kernel<<<dim3(32, 8, 16), dim3(32, 8)>>>();
    attn_mma_kernel<<<dim3(8, 8, 16), 256>>>();
    proj_o_kernel<<<dim3(8, 2, 16), 256>>>(wo, bo, out);
}

// round 8
// speedup vs baseline: 2.7288x; 1.2477x over previous
#include <cuda_runtime.h>
#include <cuda_fp16.h>
#include <cstdint>

#define C_DIM 256
#define L_DIM 1024
#define B_DIM 16
#define NH 8
#define DH 32
#define SCALE 0.17677669529663687f
#define LOG2E 1.4426950408889634f

__device__ float g_q[B_DIM * L_DIM * C_DIM];   // [b][l][c]
__device__ float g_k[B_DIM * L_DIM * C_DIM];
__device__ float g_v[B_DIM * L_DIM * C_DIM];
__device__ __half g_qh[B_DIM * L_DIM * C_DIM];   // [b][l][c]
__device__ __half g_ql[B_DIM * L_DIM * C_DIM];
__device__ __half g_kh2[B_DIM * C_DIM * L_DIM];  // [b][c][l]
__device__ __half g_kl2[B_DIM * C_DIM * L_DIM];
__device__ __half g_vth[B_DIM * L_DIM * C_DIM];  // [b][l][c]
__device__ __half g_vtl[B_DIM * L_DIM * C_DIM];
__device__ __half g_xth[B_DIM * L_DIM * C_DIM];  // x^T split; later reused as att split [b][c][l]
__device__ __half g_xtl[B_DIM * L_DIM * C_DIM];
__device__ __half g_wh[3 * C_DIM * C_DIM];       // W^T [sel][c][o]
__device__ __half g_wl[3 * C_DIM * C_DIM];
__device__ __half g_woh[C_DIM * C_DIM];          // Wo [o][c]
__device__ __half g_wol[C_DIM * C_DIM];

__device__ __forceinline__ float ex2f(float x) {
    float r; asm("ex2.approx.f32 %0, %1;" : "=f"(r) : "f"(x)); return r;
}
__device__ __forceinline__ uint32_t smem_u32(const void* p) {
    uint32_t a;
    asm("{ .reg .u64 t; cvta.to.shared.u64 t, %1; cvt.u32.u64 %0, t; }" : "=r"(a) : "l"(p));
    return a;
}
__device__ __forceinline__ uint32_t pack_h2(float lo, float hi) {
    uint32_t r; asm("cvt.rn.f16x2.f32 %0, %1, %2;" : "=r"(r) : "f"(hi), "f"(lo)); return r;
}
__device__ __forceinline__ void ldsm_x4(uint32_t* r, uint32_t a) {
    asm volatile("ldmatrix.sync.aligned.m8n8.x4.shared.b16 {%0,%1,%2,%3}, [%4];"
        : "=r"(r[0]), "=r"(r[1]), "=r"(r[2]), "=r"(r[3]) : "r"(a));
}
__device__ __forceinline__ void ldsm_x2t(uint32_t* r, uint32_t a) {
    asm volatile("ldmatrix.sync.aligned.m8n8.x2.trans.shared.b16 {%0,%1}, [%2];"
        : "=r"(r[0]), "=r"(r[1]) : "r"(a));
}
__device__ __forceinline__ void mma16816(float* d, const uint32_t* a, const uint32_t* b) {
    asm volatile("mma.sync.aligned.m16n8k16.row.col.f32.f16.f16.f32 "
        "{%0,%1,%2,%3}, {%4,%5,%6,%7}, {%8,%9}, {%0,%1,%2,%3};"
        : "+f"(d[0]), "+f"(d[1]), "+f"(d[2]), "+f"(d[3])
        : "r"(a[0]), "r"(a[1]), "r"(a[2]), "r"(a[3]), "r"(b[0]), "r"(b[1]));
}
__device__ __forceinline__ float shflx(float v, int m) {
    return __shfl_xor_sync(0xffffffffu, v, m);
}
__device__ __forceinline__ void cpa16(uint32_t s, const void* g) {
    asm volatile("cp.async.cg.shared.global [%0], [%1], 16;" :: "r"(s), "l"(g));
}
#define CP_COMMIT() asm volatile("cp.async.commit_group;" ::: "memory")
#define CP_WAIT0()  asm volatile("cp.async.wait_group 0;" ::: "memory")

// ------------------- prep kernels -------------------
__global__ void __launch_bounds__(256)
split_w_kernel(const float* __restrict__ wq, const float* __restrict__ wk, const float* __restrict__ wv)
{
    __shared__ float t[32][33];
    const int sel = blockIdx.z;
    const float* W = (sel == 0) ? wq : (sel == 1) ? wk : wv;
    __half* dh = g_wh + sel * C_DIM * C_DIM;
    __half* dl = g_wl + sel * C_DIM * C_DIM;
    const int o0 = blockIdx.x * 32, c0 = blockIdx.y * 32;
    const int tx = threadIdx.x, ty = threadIdx.y;
    #pragma unroll
    for (int i = 0; i < 4; i++)
        t[ty + 8 * i][tx] = W[(o0 + ty + 8 * i) * C_DIM + c0 + tx];
    __syncthreads();
    #pragma unroll
    for (int i = 0; i < 4; i++) {
        float v = t[tx][ty + 8 * i];
        __half h = __float2half_rn(v);
        int o = (c0 + ty + 8 * i) * C_DIM + o0 + tx;
        dh[o] = h;
        dl[o] = __float2half_rn(v - __half2float(h));
    }
}

__global__ void __launch_bounds__(256)
split_wo_kernel(const float* __restrict__ wo)
{
    int i = blockIdx.x * 256 + threadIdx.x;   // over float2
    const float2 v = ((const float2*)wo)[i];
    __half2 h = __floats2half2_rn(v.x, v.y);
    float2 hf = __half22float2(h);
    ((__half2*)g_woh)[i] = h;
    ((__half2*)g_wol)[i] = __floats2half2_rn(v.x - hf.x, v.y - hf.y);
}

__global__ void __launch_bounds__(256)
convert_x_kernel(const float* __restrict__ x)
{
    __shared__ float t[32][33];
    const int b = blockIdx.z;
    const float* src = x + (size_t)b * C_DIM * L_DIM;
    __half* dh = g_xth + (size_t)b * L_DIM * C_DIM;
    __half* dl = g_xtl + (size_t)b * L_DIM * C_DIM;
    const int l0 = blockIdx.x * 32, c0 = blockIdx.y * 32;
    const int tx = threadIdx.x, ty = threadIdx.y;
    #pragma unroll
    for (int i = 0; i < 4; i++)
        t[ty + 8 * i][tx] = src[(size_t)(c0 + ty + 8 * i) * L_DIM + l0 + tx];
    __syncthreads();
    #pragma unroll
    for (int i = 0; i < 4; i++) {
        float v = t[tx][ty + 8 * i];
        __half h = __float2half_rn(v);
        size_t o = (size_t)(l0 + ty + 8 * i) * C_DIM + c0 + tx;
        dh[o] = h;
        dl[o] = __float2half_rn(v - __half2float(h));
    }
}

// ------------------- mma QKV projection (proven R7 kernel) -------------------
__global__ void __launch_bounds__(256)
proj_qkv_mma_kernel(const float* __restrict__ bq, const float* __restrict__ bk,
                    const float* __restrict__ bv)
{
    __shared__ __align__(16) __half ash[2][128 * 40];
    __shared__ __align__(16) __half bsh[2][32 * 136];
    __shared__ float bias_s[128];

    const int tid = threadIdx.x, lane = tid & 31, w = tid >> 5;
    const int lt = blockIdx.x >> 1, oh = blockIdx.x & 1;
    const int sel = blockIdx.y, b = blockIdx.z;

    const __half* xh = g_xth + (size_t)b * L_DIM * C_DIM;
    const __half* xl = g_xtl + (size_t)b * L_DIM * C_DIM;
    const __half* wh = g_wh + sel * C_DIM * C_DIM;
    const __half* wl = g_wl + sel * C_DIM * C_DIM;
    const float* bias = (sel == 0) ? bq : (sel == 1) ? bk : bv;
    float* Y = (sel == 0) ? g_q : (sel == 1) ? g_k : g_v;
    const float sc = (sel == 0) ? (SCALE * LOG2E) : 1.0f;

    if (tid < 128) bias_s[tid] = bias[oh * 128 + tid];

    float acc[16][4] = {};
    const int rr = lane & 15;
    const int chi = (lane & 16) ? 8 : 0;

    for (int kc0 = 0; kc0 < C_DIM; kc0 += 32) {
        __syncthreads();
        #pragma unroll
        for (int i = 0; i < 2; i++) {
            int u = tid + i * 256;
            int row = u >> 2, seg = u & 3;
            size_t g = (size_t)(lt * 128 + row) * C_DIM + kc0 + seg * 8;
            *(uint4*)&ash[0][row * 40 + seg * 8] = *(const uint4*)&xh[g];
            *(uint4*)&ash[1][row * 40 + seg * 8] = *(const uint4*)&xl[g];
        }
        #pragma unroll
        for (int i = 0; i < 2; i++) {
            int u = tid + i * 256;
            int row = u >> 4, seg = u & 15;
            int g = (kc0 + row) * C_DIM + oh * 128 + seg * 8;
            *(uint4*)&bsh[0][row * 136 + seg * 8] = *(const uint4*)&wh[g];
            *(uint4*)&bsh[1][row * 136 + seg * 8] = *(const uint4*)&wl[g];
        }
        __syncthreads();

        uint32_t af[2][2][4];
        #pragma unroll
        for (int hl = 0; hl < 2; hl++)
            #pragma unroll
            for (int kc = 0; kc < 2; kc++)
                ldsm_x4(af[hl][kc], smem_u32(&ash[hl][(w * 16 + rr) * 40 + kc * 16 + chi]));

        #pragma unroll
        for (int nt = 0; nt < 16; nt++) {
            #pragma unroll
            for (int kc = 0; kc < 2; kc++) {
                uint32_t bh[2], bl[2];
                ldsm_x2t(bh, smem_u32(&bsh[0][(kc * 16 + rr) * 136 + nt * 8]));
                ldsm_x2t(bl, smem_u32(&bsh[1][(kc * 16 + rr) * 136 + nt * 8]));
                mma16816(acc[nt], af[0][kc], bh);
                mma16816(acc[nt], af[0][kc], bl);
                mma16816(acc[nt], af[1][kc], bh);
            }
        }
    }

    const int r0 = lt * 128 + w * 16 + (lane >> 2);
    #pragma unroll
    for (int nt = 0; nt < 16; nt++) {
        int c0 = nt * 8 + (lane & 3) * 2;
        float b0 = bias_s[c0], b1 = bias_s[c0 + 1];
        float2 y0, y1;
        y0.x = (acc[nt][0] + b0) * sc; y0.y = (acc[nt][1] + b1) * sc;
        y1.x = (acc[nt][2] + b0) * sc; y1.y = (acc[nt][3] + b1) * sc;
        *(float2*)&g_q[0] ; // placeholder avoided
        *(float2*)&Y[((size_t)(b * 1024 + r0)) * C_DIM + oh * 128 + c0] = y0;
        *(float2*)&Y[((size_t)(b * 1024 + r0 + 8)) * C_DIM + oh * 128 + c0] = y1;
    }
}

// ------------------- converts from [b][l][c] fp32 -------------------
__global__ void __launch_bounds__(256)
convert_qv_kernel()
{
    const int sel = blockIdx.y;
    int i = blockIdx.x * 256 + threadIdx.x;
    const float2 v = ((const float2*)(sel ? g_v : g_q))[i];
    __half2 h = __floats2half2_rn(v.x, v.y);
    float2 hf = __half22float2(h);
    ((__half2*)(sel ? g_vth : g_qh))[i] = h;
    ((__half2*)(sel ? g_vtl : g_ql))[i] = __floats2half2_rn(v.x - hf.x, v.y - hf.y);
}

__global__ void __launch_bounds__(256)
convert_k_t_kernel()
{
    __shared__ float t[32][33];
    const int b = blockIdx.z;
    const float* src = g_k + (size_t)b * L_DIM * C_DIM;
    __half* dh = g_kh2 + (size_t)b * C_DIM * L_DIM;
    __half* dl = g_kl2 + (size_t)b * C_DIM * L_DIM;
    const int l0 = blockIdx.x * 32, c0 = blockIdx.y * 32;
    const int tx = threadIdx.x, ty = threadIdx.y;
    #pragma unroll
    for (int i = 0; i < 4; i++)
        t[ty + 8 * i][tx] = src[(size_t)(l0 + ty + 8 * i) * C_DIM + c0 + tx];
    __syncthreads();
    #pragma unroll
    for (int i = 0; i < 4; i++) {
        float v = t[tx][ty + 8 * i];
        __half h = __float2half_rn(v);
        size_t o = (size_t)(c0 + ty + 8 * i) * L_DIM + l0 + tx;
        dh[o] = h;
        dl[o] = __float2half_rn(v - __half2float(h));
    }
}

// ------------------- flash attention: cp.async double-buffered -------------------
// smem pool: Q region [0, 10240) halves; buf0 at 10240 (9728 halves); buf1 overlays Q.
// buf layout: Kh +0 (2304), Kl +2304, Vh +4608 (2560), Vl +7168.
__global__ void __launch_bounds__(256, 1)
attn_mma_kernel()
{
    __shared__ __align__(16) __half pool[10240 + 9728];

    const int tid = threadIdx.x, lane = tid & 31, w = tid >> 5;
    const int qt = blockIdx.x, n = blockIdx.y, b = blockIdx.z;
    const int rr = lane & 15;

    // prologue: issue t=0 K/V into buf0 (does not overlap Q region)
    {
        __half* base = pool + 10240;
        int row = tid >> 3, seg = tid & 7;
        size_t gk = ((size_t)(b * 256 + n * 32 + row)) * L_DIM + seg * 8;
        cpa16(smem_u32(base + row * 72 + seg * 8), &g_kh2[gk]);
        cpa16(smem_u32(base + 2304 + row * 72 + seg * 8), &g_kl2[gk]);
        int vrow = tid >> 2, vseg = tid & 3;
        size_t gv = ((size_t)(b * 1024 + vrow)) * C_DIM + n * 32 + vseg * 8;
        cpa16(smem_u32(base + 4608 + vrow * 40 + vseg * 8), &g_vth[gv]);
        cpa16(smem_u32(base + 7168 + vrow * 40 + vseg * 8), &g_vtl[gv]);
        CP_COMMIT();
    }

    // stage Q into pool[0,10240): [hl][row*40 + c]
    for (int u = tid; u < 512; u += 256) {
        int row = u >> 2, seg = u & 3;
        size_t g = ((size_t)(b * 1024 + qt * 128 + row)) * C_DIM + n * 32 + seg * 8;
        *(uint4*)&pool[row * 40 + seg * 8] = *(const uint4*)&g_qh[g];
        *(uint4*)&pool[5120 + row * 40 + seg * 8] = *(const uint4*)&g_ql[g];
    }
    __syncthreads();

    uint32_t qf[2][2][4];
    {
        int chi = (lane & 16) ? 8 : 0;
        #pragma unroll
        for (int hl = 0; hl < 2; hl++)
            #pragma unroll
            for (int kc = 0; kc < 2; kc++)
                ldsm_x4(qf[hl][kc], smem_u32(&pool[hl * 5120 + (w * 16 + rr) * 40 + kc * 16 + chi]));
    }
    __syncthreads();   // all warps done reading Q; buf1 (overlay) may now be written

    float oacc[4][4] = {};
    float m0 = -1e30f, m1 = -1e30f, l0 = 0.0f, l1 = 0.0f;

    for (int t = 0; t < 16; t++) {
        CP_WAIT0();
        __syncthreads();

        if (t < 15) {   // issue t+1 into the other buffer
            __half* base = pool + (((t + 1) & 1) ? 0 : 10240);
            int row = tid >> 3, seg = tid & 7;
            size_t gk = ((size_t)(b * 256 + n * 32 + row)) * L_DIM + (t + 1) * 64 + seg * 8;
            cpa16(smem_u32(base + row * 72 + seg * 8), &g_kh2[gk]);
            cpa16(smem_u32(base + 2304 + row * 72 + seg * 8), &g_kl2[gk]);
            int vrow = tid >> 2, vseg = tid & 3;
            size_t gv = ((size_t)(b * 1024 + (t + 1) * 64 + vrow)) * C_DIM + n * 32 + vseg * 8;
            cpa16(smem_u32(base + 4608 + vrow * 40 + vseg * 8), &g_vth[gv]);
            cpa16(smem_u32(base + 7168 + vrow * 40 + vseg * 8), &g_vtl[gv]);
            CP_COMMIT();
        }

        __half* cur = pool + ((t & 1) ? 0 : 10240);
        __half* ksh0 = cur;
        __half* ksh1 = cur + 2304;
        __half* vsh0 = cur + 4608;
        __half* vsh1 = cur + 7168;

        // ---- S = QhKh + QhKl + QlKh ----
        float sacc[8][4];
        #pragma unroll
        for (int nt = 0; nt < 8; nt++) {
            sacc[nt][0] = sacc[nt][1] = sacc[nt][2] = sacc[nt][3] = 0.0f;
            uint32_t kbh[2][2], kbl[2][2];
            #pragma unroll
            for (int kc = 0; kc < 2; kc++) {
                ldsm_x2t(kbh[kc], smem_u32(&ksh0[(kc * 16 + rr) * 72 + nt * 8]));
                ldsm_x2t(kbl[kc], smem_u32(&ksh1[(kc * 16 + rr) * 72 + nt * 8]));
            }
            #pragma unroll
            for (int kc = 0; kc < 2; kc++) {
                mma16816(sacc[nt], qf[0][kc], kbh[kc]);
                mma16816(sacc[nt], qf[0][kc], kbl[kc]);
                mma16816(sacc[nt], qf[1][kc], kbh[kc]);
            }
        }

        // ---- online softmax ----
        float mt0 = -1e30f, mt1 = -1e30f;
        #pragma unroll
        for (int nt = 0; nt < 8; nt++) {
            mt0 = fmaxf(mt0, fmaxf(sacc[nt][0], sacc[nt][1]));
            mt1 = fmaxf(mt1, fmaxf(sacc[nt][2], sacc[nt][3]));
        }
        mt0 = fmaxf(mt0, shflx(mt0, 1)); mt0 = fmaxf(mt0, shflx(mt0, 2));
        mt1 = fmaxf(mt1, shflx(mt1, 1)); mt1 = fmaxf(mt1, shflx(mt1, 2));
        float nm0 = fmaxf(m0, mt0), nm1 = fmaxf(m1, mt1);
        float c0 = ex2f(m0 - nm0), c1 = ex2f(m1 - nm1);
        m0 = nm0; m1 = nm1;
        l0 *= c0; l1 *= c1;
        #pragma unroll
        for (int nt = 0; nt < 4; nt++) {
            oacc[nt][0] *= c0; oacc[nt][1] *= c0;
            oacc[nt][2] *= c1; oacc[nt][3] *= c1;
        }
        float rs0 = 0.0f, rs1 = 0.0f;
        #pragma unroll
        for (int nt = 0; nt < 8; nt++) {
            sacc[nt][0] = ex2f(sacc[nt][0] - m0);
            sacc[nt][1] = ex2f(sacc[nt][1] - m0);
            sacc[nt][2] = ex2f(sacc[nt][2] - m1);
            sacc[nt][3] = ex2f(sacc[nt][3] - m1);
            rs0 += sacc[nt][0] + sacc[nt][1];
            rs1 += sacc[nt][2] + sacc[nt][3];
        }
        rs0 += shflx(rs0, 1); rs0 += shflx(rs0, 2);
        rs1 += shflx(rs1, 1); rs1 += shflx(rs1, 2);
        l0 += rs0; l1 += rs1;

        // ---- P hi-only fragments ----
        uint32_t pfh[4][4];
        #pragma unroll
        for (int kc = 0; kc < 4; kc++) {
            const float* s0 = sacc[2 * kc];
            const float* s1 = sacc[2 * kc + 1];
            pfh[kc][0] = pack_h2(s0[0], s0[1]);
            pfh[kc][1] = pack_h2(s0[2], s0[3]);
            pfh[kc][2] = pack_h2(s1[0], s1[1]);
            pfh[kc][3] = pack_h2(s1[2], s1[3]);
        }

        // ---- O += Ph*Vh + Ph*Vl ----
        #pragma unroll
        for (int nt = 0; nt < 4; nt++) {
            #pragma unroll
            for (int kc = 0; kc < 4; kc++) {
                uint32_t vbh[2], vbl[2];
                ldsm_x2t(vbh, smem_u32(&vsh0[(kc * 16 + rr) * 40 + nt * 8]));
                ldsm_x2t(vbl, smem_u32(&vsh1[(kc * 16 + rr) * 40 + nt * 8]));
                mma16816(oacc[nt], pfh[kc], vbh);
                mma16816(oacc[nt], pfh[kc], vbl);
            }
        }
    }

    // ---- epilogue: write O directly as f16 hi/lo split [b][c][l] ----
    float i0 = 1.0f / l0, i1 = 1.0f / l1;
    int q0 = qt * 128 + w * 16 + (lane >> 2);
    #pragma unroll
    for (int nt = 0; nt < 4; nt++) {
        int c = n * 32 + nt * 8 + (lane & 3) * 2;
        float v00 = oacc[nt][0] * i0, v01 = oacc[nt][1] * i0;
        float v10 = oacc[nt][2] * i1, v11 = oacc[nt][3] * i1;
        size_t b0 = ((size_t)(b * 256 + c)) * L_DIM + q0;
        size_t b1 = b0 + L_DIM;
        __half h;
        h = __float2half_rn(v00); g_xth[b0] = h;     g_xtl[b0] = __float2half_rn(v00 - __half2float(h));
        h = __float2half_rn(v01); g_xth[b1] = h;     g_xtl[b1] = __float2half_rn(v01 - __half2float(h));
        h = __float2half_rn(v10); g_xth[b0 + 8] = h; g_xtl[b0 + 8] = __float2half_rn(v10 - __half2float(h));
        h = __float2half_rn(v11); g_xth[b1 + 8] = h; g_xtl[b1 + 8] = __float2half_rn(v11 - __half2float(h));
    }
}

// ------------------- mma output projection: out[b][o][l] -------------------
__global__ void __launch_bounds__(256)
proj_o_mma_kernel(const float* __restrict__ bo, float* __restrict__ out)
{
    __shared__ __align__(16) __half ash[2][128 * 40];   // Wo [o][c-chunk]
    __shared__ __align__(16) __half bsh[2][32 * 136];   // att [c][l 128]
    __shared__ float bias_s[128];

    const int tid = threadIdx.x, lane = tid & 31, w = tid >> 5;
    const int lt = blockIdx.x >> 1, oh = blockIdx.x & 1;
    const int b = blockIdx.z;

    if (tid < 128) bias_s[tid] = bo[oh * 128 + tid];

    float acc[16][4] = {};
    const int rr = lane & 15;
    const int chi = (lane & 16) ? 8 : 0;

    for (int kc0 = 0; kc0 < C_DIM; kc0 += 32) {
        __syncthreads();
        // A: Wo 128 o-rows x 32 c
        #pragma unroll
        for (int i = 0; i < 2; i++) {
            int u = tid + i * 256;
            int row = u >> 2, seg = u & 3;
            int g = (oh * 128 + row) * C_DIM + kc0 + seg * 8;
            *(uint4*)&ash[0][row * 40 + seg * 8] = *(const uint4*)&g_woh[g];
            *(uint4*)&ash[1][row * 40 + seg * 8] = *(const uint4*)&g_wol[g];
        }
        // B: att 32 c-rows x 128 l
        #pragma unroll
        for (int i = 0; i < 2; i++) {
            int u = tid + i * 256;
            int row = u >> 4, seg = u & 15;
            size_t g = ((size_t)(b * 256 + kc0 + row)) * L_DIM + lt * 128 + seg * 8;
            *(uint4*)&bsh[0][row * 136 + seg * 8] = *(const uint4*)&g_xth[g];
            *(uint4*)&bsh[1][row * 136 + seg * 8] = *(const uint4*)&g_xtl[g];
        }
        __syncthreads();

        uint32_t af[2][2][4];
        #pragma unroll
        for (int hl = 0; hl < 2; hl++)
            #pragma unroll
            for (int kc = 0; kc < 2; kc++)
                ldsm_x4(af[hl][kc], smem_u32(&ash[hl][(w * 16 + rr) * 40 + kc * 16 + chi]));

        #pragma unroll
        for (int nt = 0; nt < 16; nt++) {
            #pragma unroll
            for (int kc = 0; kc < 2; kc++) {
                uint32_t bh[2], bl[2];
                ldsm_x2t(bh, smem_u32(&bsh[0][(kc * 16 + rr) * 136 + nt * 8]));
                ldsm_x2t(bl, smem_u32(&bsh[1][(kc * 16 + rr) * 136 + nt * 8]));
                mma16816(acc[nt], af[0][kc], bh);
                mma16816(acc[nt], af[0][kc], bl);
                mma16816(acc[nt], af[1][kc], bh);
            }
        }
    }

    // epilogue: out[b][o][l]
    const int orow = oh * 128 + w * 16 + (lane >> 2);
    const float bb0 = bias_s[w * 16 + (lane >> 2)];
    const float bb1 = bias_s[w * 16 + (lane >> 2) + 8];
    #pragma unroll
    for (int nt = 0; nt < 16; nt++) {
        int lcol = lt * 128 + nt * 8 + (lane & 3) * 2;
        float2 y0, y1;
        y0.x = acc[nt][0] + bb0; y0.y = acc[nt][1] + bb0;
        y1.x = acc[nt][2] + bb1; y1.y = acc[nt][3] + bb1;
        *(float2*)&out[((size_t)(b * 256 + orow)) * L_DIM + lcol] = y0;
        *(float2*)&out[((size_t)(b * 256 + orow + 8)) * L_DIM + lcol] = y1;
    }
}

// ---------------------------------------------------------------------------
extern "C" void kernel_launch(void* const* d_in, const int* in_sizes, int n_in,
                              void* d_out, int out_size)
{
    const float* x  = (const float*)d_in[0];
    const float* wq = (const float*)d_in[1];
    const float* bq = (const float*)d_in[2];
    const float* wk = (const float*)d_in[3];
    const float* bk = (const float*)d_in[4];
    const float* wv = (const float*)d_in[5];
    const float* bv = (const float*)d_in[6];
    const float* wo = (const float*)d_in[7];
    const float* bo = (const float*)d_in[8];
    float* out = (float*)d_out;

    split_w_kernel<<<dim3(8, 8, 3), dim3(32, 8)>>>(wq, wk, wv);
    split_wo_kernel<<<128, 256>>>(wo);
    convert_x_kernel<<<dim3(32, 8, 16), dim3(32, 8)>>>(x);
    proj_qkv_mma_kernel<<<dim3(16, 3, 16), 256>>>(bq, bk, bv);
    convert_qv_kernel<<<dim3(8192, 2), 256>>>();
    convert_k_t_kernel<<<dim3(32, 8, 16), dim3(32, 8)>>>();
    attn_mma_kernel<<<dim3(8, 8, 16), 256>>>();
    proj_o_mma_kernel<<<dim3(16, 1, 16), 256>>>(bo, out);
}

// round 9
// speedup vs baseline: 3.2488x; 1.1906x over previous
#include <cuda_runtime.h>
#include <cuda_fp16.h>
#include <cstdint>

#define C_DIM 256
#define L_DIM 1024
#define B_DIM 16
#define NH 8
#define DH 32
#define SCALE 0.17677669529663687f
#define LOG2E 1.4426950408889634f

// f16 hi/lo split buffers (no fp32 intermediates anymore)
__device__ __half g_qh[B_DIM * L_DIM * C_DIM];   // [b][l][c]
__device__ __half g_ql[B_DIM * L_DIM * C_DIM];
__device__ __half g_kth[B_DIM * L_DIM * C_DIM];  // k [b][l][c] (pre-transpose)
__device__ __half g_ktl[B_DIM * L_DIM * C_DIM];
__device__ __half g_kh2[B_DIM * C_DIM * L_DIM];  // k [b][c][l]
__device__ __half g_kl2[B_DIM * C_DIM * L_DIM];
__device__ __half g_vth[B_DIM * L_DIM * C_DIM];  // v [b][l][c]
__device__ __half g_vtl[B_DIM * L_DIM * C_DIM];
__device__ __half g_xth[B_DIM * L_DIM * C_DIM];  // x^T split; reused as att split [b][c][l]
__device__ __half g_xtl[B_DIM * L_DIM * C_DIM];
__device__ __half g_wh[3 * C_DIM * C_DIM];       // W^T [sel][c][o]
__device__ __half g_wl[3 * C_DIM * C_DIM];
__device__ __half g_woh[C_DIM * C_DIM];          // Wo [o][c]
__device__ __half g_wol[C_DIM * C_DIM];

__device__ __forceinline__ float ex2f(float x) {
    float r; asm("ex2.approx.f32 %0, %1;" : "=f"(r) : "f"(x)); return r;
}
__device__ __forceinline__ uint32_t smem_u32(const void* p) {
    uint32_t a;
    asm("{ .reg .u64 t; cvta.to.shared.u64 t, %1; cvt.u32.u64 %0, t; }" : "=r"(a) : "l"(p));
    return a;
}
__device__ __forceinline__ uint32_t pack_h2(float lo, float hi) {
    uint32_t r; asm("cvt.rn.f16x2.f32 %0, %1, %2;" : "=r"(r) : "f"(hi), "f"(lo)); return r;
}
__device__ __forceinline__ void ldsm_x4(uint32_t* r, uint32_t a) {
    asm volatile("ldmatrix.sync.aligned.m8n8.x4.shared.b16 {%0,%1,%2,%3}, [%4];"
        : "=r"(r[0]), "=r"(r[1]), "=r"(r[2]), "=r"(r[3]) : "r"(a));
}
__device__ __forceinline__ void ldsm_x4t(uint32_t* r, uint32_t a) {
    asm volatile("ldmatrix.sync.aligned.m8n8.x4.trans.shared.b16 {%0,%1,%2,%3}, [%4];"
        : "=r"(r[0]), "=r"(r[1]), "=r"(r[2]), "=r"(r[3]) : "r"(a));
}
__device__ __forceinline__ void mma16816(float* d, const uint32_t* a, const uint32_t* b) {
    asm volatile("mma.sync.aligned.m16n8k16.row.col.f32.f16.f16.f32 "
        "{%0,%1,%2,%3}, {%4,%5,%6,%7}, {%8,%9}, {%0,%1,%2,%3};"
        : "+f"(d[0]), "+f"(d[1]), "+f"(d[2]), "+f"(d[3])
        : "r"(a[0]), "r"(a[1]), "r"(a[2]), "r"(a[3]), "r"(b[0]), "r"(b[1]));
}
__device__ __forceinline__ float shflx(float v, int m) {
    return __shfl_xor_sync(0xffffffffu, v, m);
}
__device__ __forceinline__ void cpa16(uint32_t s, const void* g) {
    asm volatile("cp.async.cg.shared.global [%0], [%1], 16;" :: "r"(s), "l"(g));
}
#define CP_COMMIT() asm volatile("cp.async.commit_group;" ::: "memory")
#define CP_WAIT0()  asm volatile("cp.async.wait_group 0;" ::: "memory")

// ------------------- prep kernels -------------------
__global__ void __launch_bounds__(256)
split_w_kernel(const float* __restrict__ wq, const float* __restrict__ wk, const float* __restrict__ wv)
{
    __shared__ float t[32][33];
    const int sel = blockIdx.z;
    const float* W = (sel == 0) ? wq : (sel == 1) ? wk : wv;
    __half* dh = g_wh + sel * C_DIM * C_DIM;
    __half* dl = g_wl + sel * C_DIM * C_DIM;
    const int o0 = blockIdx.x * 32, c0 = blockIdx.y * 32;
    const int tx = threadIdx.x, ty = threadIdx.y;
    #pragma unroll
    for (int i = 0; i < 4; i++)
        t[ty + 8 * i][tx] = W[(o0 + ty + 8 * i) * C_DIM + c0 + tx];
    __syncthreads();
    #pragma unroll
    for (int i = 0; i < 4; i++) {
        float v = t[tx][ty + 8 * i];
        __half h = __float2half_rn(v);
        int o = (c0 + ty + 8 * i) * C_DIM + o0 + tx;
        dh[o] = h;
        dl[o] = __float2half_rn(v - __half2float(h));
    }
}

__global__ void __launch_bounds__(256)
split_wo_kernel(const float* __restrict__ wo)
{
    int i = blockIdx.x * 256 + threadIdx.x;
    const float2 v = ((const float2*)wo)[i];
    __half2 h = __floats2half2_rn(v.x, v.y);
    float2 hf = __half22float2(h);
    ((__half2*)g_woh)[i] = h;
    ((__half2*)g_wol)[i] = __floats2half2_rn(v.x - hf.x, v.y - hf.y);
}

__global__ void __launch_bounds__(256)
convert_x_kernel(const float* __restrict__ x)
{
    __shared__ float t[32][33];
    const int b = blockIdx.z;
    const float* src = x + (size_t)b * C_DIM * L_DIM;
    __half* dh = g_xth + (size_t)b * L_DIM * C_DIM;
    __half* dl = g_xtl + (size_t)b * L_DIM * C_DIM;
    const int l0 = blockIdx.x * 32, c0 = blockIdx.y * 32;
    const int tx = threadIdx.x, ty = threadIdx.y;
    #pragma unroll
    for (int i = 0; i < 4; i++)
        t[ty + 8 * i][tx] = src[(size_t)(c0 + ty + 8 * i) * L_DIM + l0 + tx];
    __syncthreads();
    #pragma unroll
    for (int i = 0; i < 4; i++) {
        float v = t[tx][ty + 8 * i];
        __half h = __float2half_rn(v);
        size_t o = (size_t)(l0 + ty + 8 * i) * C_DIM + c0 + tx;
        dh[o] = h;
        dl[o] = __float2half_rn(v - __half2float(h));
    }
}

// ------------------- mma QKV projection: writes split halves directly -------------------
__global__ void __launch_bounds__(256)
proj_qkv_mma_kernel(const float* __restrict__ bq, const float* __restrict__ bk,
                    const float* __restrict__ bv)
{
    __shared__ __align__(16) __half ash[2][128 * 40];
    __shared__ __align__(16) __half bsh[2][32 * 136];
    __shared__ float bias_s[128];

    const int tid = threadIdx.x, lane = tid & 31, w = tid >> 5;
    const int lt = blockIdx.x >> 1, oh = blockIdx.x & 1;
    const int sel = blockIdx.y, b = blockIdx.z;

    const __half* xh = g_xth + (size_t)b * L_DIM * C_DIM;
    const __half* xl = g_xtl + (size_t)b * L_DIM * C_DIM;
    const __half* wh = g_wh + sel * C_DIM * C_DIM;
    const __half* wl = g_wl + sel * C_DIM * C_DIM;
    const float* bias = (sel == 0) ? bq : (sel == 1) ? bk : bv;
    __half* Yh = (sel == 0) ? g_qh : (sel == 1) ? g_kth : g_vth;
    __half* Yl = (sel == 0) ? g_ql : (sel == 1) ? g_ktl : g_vtl;
    const float sc = (sel == 0) ? (SCALE * LOG2E) : 1.0f;

    if (tid < 128) bias_s[tid] = bias[oh * 128 + tid];

    float acc[16][4] = {};
    const int rr = lane & 15;
    const int chi = (lane & 16) ? 8 : 0;

    for (int kc0 = 0; kc0 < C_DIM; kc0 += 32) {
        __syncthreads();
        #pragma unroll
        for (int i = 0; i < 2; i++) {
            int u = tid + i * 256;
            int row = u >> 2, seg = u & 3;
            size_t g = (size_t)(lt * 128 + row) * C_DIM + kc0 + seg * 8;
            *(uint4*)&ash[0][row * 40 + seg * 8] = *(const uint4*)&xh[g];
            *(uint4*)&ash[1][row * 40 + seg * 8] = *(const uint4*)&xl[g];
        }
        #pragma unroll
        for (int i = 0; i < 2; i++) {
            int u = tid + i * 256;
            int row = u >> 4, seg = u & 15;
            int g = (kc0 + row) * C_DIM + oh * 128 + seg * 8;
            *(uint4*)&bsh[0][row * 136 + seg * 8] = *(const uint4*)&wh[g];
            *(uint4*)&bsh[1][row * 136 + seg * 8] = *(const uint4*)&wl[g];
        }
        __syncthreads();

        uint32_t af[2][2][4];
        #pragma unroll
        for (int hl = 0; hl < 2; hl++)
            #pragma unroll
            for (int kc = 0; kc < 2; kc++)
                ldsm_x4(af[hl][kc], smem_u32(&ash[hl][(w * 16 + rr) * 40 + kc * 16 + chi]));

        #pragma unroll
        for (int nt = 0; nt < 16; nt += 2) {
            #pragma unroll
            for (int kc = 0; kc < 2; kc++) {
                uint32_t bh[4], bl[4];
                ldsm_x4t(bh, smem_u32(&bsh[0][(kc * 16 + rr) * 136 + nt * 8 + chi]));
                ldsm_x4t(bl, smem_u32(&bsh[1][(kc * 16 + rr) * 136 + nt * 8 + chi]));
                mma16816(acc[nt],     af[0][kc], bh);
                mma16816(acc[nt + 1], af[0][kc], bh + 2);
                mma16816(acc[nt],     af[0][kc], bl);
                mma16816(acc[nt + 1], af[0][kc], bl + 2);
                mma16816(acc[nt],     af[1][kc], bh);
                mma16816(acc[nt + 1], af[1][kc], bh + 2);
            }
        }
    }

    // epilogue: write f16 hi/lo split directly, [b][l][c]
    const int r0 = lt * 128 + w * 16 + (lane >> 2);
    #pragma unroll
    for (int nt = 0; nt < 16; nt++) {
        int c0 = nt * 8 + (lane & 3) * 2;
        float b0 = bias_s[c0], b1 = bias_s[c0 + 1];
        float v0 = (acc[nt][0] + b0) * sc, v1 = (acc[nt][1] + b1) * sc;
        float v2 = (acc[nt][2] + b0) * sc, v3 = (acc[nt][3] + b1) * sc;
        __half2 h0 = __floats2half2_rn(v0, v1);
        __half2 h1 = __floats2half2_rn(v2, v3);
        float2 f0 = __half22float2(h0);
        float2 f1 = __half22float2(h1);
        size_t o0 = (size_t)(b * 1024 + r0) * C_DIM + oh * 128 + c0;
        size_t o1 = (size_t)(b * 1024 + r0 + 8) * C_DIM + oh * 128 + c0;
        *(__half2*)&Yh[o0] = h0;
        *(__half2*)&Yh[o1] = h1;
        *(__half2*)&Yl[o0] = __floats2half2_rn(v0 - f0.x, v1 - f0.y);
        *(__half2*)&Yl[o1] = __floats2half2_rn(v2 - f1.x, v3 - f1.y);
    }
}

// ------------------- k transpose (half -> half): [b][l][c] -> [b][c][l] -------------------
__global__ void __launch_bounds__(256)
convert_kt_kernel()
{
    __shared__ __half th[32][34];
    __shared__ __half tl[32][34];
    const int b = blockIdx.z;
    const int l0 = blockIdx.x * 32, c0 = blockIdx.y * 32;
    const int tx = threadIdx.x, ty = threadIdx.y;
    #pragma unroll
    for (int i = 0; i < 4; i++) {
        size_t g = (size_t)(b * 1024 + l0 + ty + 8 * i) * C_DIM + c0 + tx;
        th[ty + 8 * i][tx] = g_kth[g];
        tl[ty + 8 * i][tx] = g_ktl[g];
    }
    __syncthreads();
    #pragma unroll
    for (int i = 0; i < 4; i++) {
        size_t o = (size_t)(b * 256 + c0 + ty + 8 * i) * L_DIM + l0 + tx;
        g_kh2[o] = th[tx][ty + 8 * i];
        g_kl2[o] = tl[tx][ty + 8 * i];
    }
}

// ------------------- flash attention: cp.async double-buffered, 2 CTA/SM -------------------
// pool: Q region [0, 10240) halves; buf0 at 10240 (9728 halves); buf1 overlays Q.
// buf layout: Kh +0 (2304), Kl +2304, Vh +4608 (2560), Vl +7168.
__global__ void __launch_bounds__(256, 2)
attn_mma_kernel()
{
    __shared__ __align__(16) __half pool[10240 + 9728];

    const int tid = threadIdx.x, lane = tid & 31, w = tid >> 5;
    const int qt = blockIdx.x, n = blockIdx.y, b = blockIdx.z;
    const int rr = lane & 15;
    const int hoff = (lane & 16) ? 8 : 0;

    // prologue: issue t=0 K/V into buf0
    {
        __half* base = pool + 10240;
        int row = tid >> 3, seg = tid & 7;
        size_t gk = ((size_t)(b * 256 + n * 32 + row)) * L_DIM + seg * 8;
        cpa16(smem_u32(base + row * 72 + seg * 8), &g_kh2[gk]);
        cpa16(smem_u32(base + 2304 + row * 72 + seg * 8), &g_kl2[gk]);
        int vrow = tid >> 2, vseg = tid & 3;
        size_t gv = ((size_t)(b * 1024 + vrow)) * C_DIM + n * 32 + vseg * 8;
        cpa16(smem_u32(base + 4608 + vrow * 40 + vseg * 8), &g_vth[gv]);
        cpa16(smem_u32(base + 7168 + vrow * 40 + vseg * 8), &g_vtl[gv]);
        CP_COMMIT();
    }

    // stage Q
    for (int u = tid; u < 512; u += 256) {
        int row = u >> 2, seg = u & 3;
        size_t g = ((size_t)(b * 1024 + qt * 128 + row)) * C_DIM + n * 32 + seg * 8;
        *(uint4*)&pool[row * 40 + seg * 8] = *(const uint4*)&g_qh[g];
        *(uint4*)&pool[5120 + row * 40 + seg * 8] = *(const uint4*)&g_ql[g];
    }
    __syncthreads();

    uint32_t qf[2][2][4];
    #pragma unroll
    for (int hl = 0; hl < 2; hl++)
        #pragma unroll
        for (int kc = 0; kc < 2; kc++)
            ldsm_x4(qf[hl][kc], smem_u32(&pool[hl * 5120 + (w * 16 + rr) * 40 + kc * 16 + hoff]));
    __syncthreads();   // Q consumed; overlay buffer may be written

    float oacc[4][4] = {};
    float m0 = -1e30f, m1 = -1e30f, l0 = 0.0f, l1 = 0.0f;

    for (int t = 0; t < 16; t++) {
        CP_WAIT0();
        __syncthreads();

        if (t < 15) {
            __half* base = pool + (((t + 1) & 1) ? 0 : 10240);
            int row = tid >> 3, seg = tid & 7;
            size_t gk = ((size_t)(b * 256 + n * 32 + row)) * L_DIM + (t + 1) * 64 + seg * 8;
            cpa16(smem_u32(base + row * 72 + seg * 8), &g_kh2[gk]);
            cpa16(smem_u32(base + 2304 + row * 72 + seg * 8), &g_kl2[gk]);
            int vrow = tid >> 2, vseg = tid & 3;
            size_t gv = ((size_t)(b * 1024 + (t + 1) * 64 + vrow)) * C_DIM + n * 32 + vseg * 8;
            cpa16(smem_u32(base + 4608 + vrow * 40 + vseg * 8), &g_vth[gv]);
            cpa16(smem_u32(base + 7168 + vrow * 40 + vseg * 8), &g_vtl[gv]);
            CP_COMMIT();
        }

        __half* cur = pool + ((t & 1) ? 0 : 10240);
        __half* ksh0 = cur;
        __half* ksh1 = cur + 2304;
        __half* vsh0 = cur + 4608;
        __half* vsh1 = cur + 7168;

        // ---- S = QhKh + QhKl + QlKh, x4t loads (2 n-tiles per load) ----
        float sacc[8][4];
        #pragma unroll
        for (int nt = 0; nt < 8; nt += 2) {
            sacc[nt][0] = sacc[nt][1] = sacc[nt][2] = sacc[nt][3] = 0.0f;
            sacc[nt+1][0] = sacc[nt+1][1] = sacc[nt+1][2] = sacc[nt+1][3] = 0.0f;
            #pragma unroll
            for (int kc = 0; kc < 2; kc++) {
                uint32_t kbh[4], kbl[4];
                ldsm_x4t(kbh, smem_u32(&ksh0[(kc * 16 + rr) * 72 + nt * 8 + hoff]));
                ldsm_x4t(kbl, smem_u32(&ksh1[(kc * 16 + rr) * 72 + nt * 8 + hoff]));
                mma16816(sacc[nt],     qf[0][kc], kbh);
                mma16816(sacc[nt + 1], qf[0][kc], kbh + 2);
                mma16816(sacc[nt],     qf[0][kc], kbl);
                mma16816(sacc[nt + 1], qf[0][kc], kbl + 2);
                mma16816(sacc[nt],     qf[1][kc], kbh);
                mma16816(sacc[nt + 1], qf[1][kc], kbh + 2);
            }
        }

        // ---- online softmax ----
        float mt0 = -1e30f, mt1 = -1e30f;
        #pragma unroll
        for (int nt = 0; nt < 8; nt++) {
            mt0 = fmaxf(mt0, fmaxf(sacc[nt][0], sacc[nt][1]));
            mt1 = fmaxf(mt1, fmaxf(sacc[nt][2], sacc[nt][3]));
        }
        mt0 = fmaxf(mt0, shflx(mt0, 1)); mt0 = fmaxf(mt0, shflx(mt0, 2));
        mt1 = fmaxf(mt1, shflx(mt1, 1)); mt1 = fmaxf(mt1, shflx(mt1, 2));
        float nm0 = fmaxf(m0, mt0), nm1 = fmaxf(m1, mt1);
        float c0 = ex2f(m0 - nm0), c1 = ex2f(m1 - nm1);
        m0 = nm0; m1 = nm1;
        l0 *= c0; l1 *= c1;
        #pragma unroll
        for (int nt = 0; nt < 4; nt++) {
            oacc[nt][0] *= c0; oacc[nt][1] *= c0;
            oacc[nt][2] *= c1; oacc[nt][3] *= c1;
        }
        float rs0 = 0.0f, rs1 = 0.0f;
        #pragma unroll
        for (int nt = 0; nt < 8; nt++) {
            sacc[nt][0] = ex2f(sacc[nt][0] - m0);
            sacc[nt][1] = ex2f(sacc[nt][1] - m0);
            sacc[nt][2] = ex2f(sacc[nt][2] - m1);
            sacc[nt][3] = ex2f(sacc[nt][3] - m1);
            rs0 += sacc[nt][0] + sacc[nt][1];
            rs1 += sacc[nt][2] + sacc[nt][3];
        }
        rs0 += shflx(rs0, 1); rs0 += shflx(rs0, 2);
        rs1 += shflx(rs1, 1); rs1 += shflx(rs1, 2);
        l0 += rs0; l1 += rs1;

        // ---- P hi-only fragments ----
        uint32_t pfh[4][4];
        #pragma unroll
        for (int kc = 0; kc < 4; kc++) {
            const float* s0 = sacc[2 * kc];
            const float* s1 = sacc[2 * kc + 1];
            pfh[kc][0] = pack_h2(s0[0], s0[1]);
            pfh[kc][1] = pack_h2(s0[2], s0[3]);
            pfh[kc][2] = pack_h2(s1[0], s1[1]);
            pfh[kc][3] = pack_h2(s1[2], s1[3]);
        }

        // ---- O += Ph*Vh + Ph*Vl, x4t loads (2 d-tiles per load) ----
        #pragma unroll
        for (int kc = 0; kc < 4; kc++) {
            #pragma unroll
            for (int np = 0; np < 2; np++) {   // d-tile pairs {0,1}, {2,3}
                uint32_t vbh[4], vbl[4];
                ldsm_x4t(vbh, smem_u32(&vsh0[(kc * 16 + rr) * 40 + np * 16 + hoff]));
                ldsm_x4t(vbl, smem_u32(&vsh1[(kc * 16 + rr) * 40 + np * 16 + hoff]));
                mma16816(oacc[2 * np],     pfh[kc], vbh);
                mma16816(oacc[2 * np + 1], pfh[kc], vbh + 2);
                mma16816(oacc[2 * np],     pfh[kc], vbl);
                mma16816(oacc[2 * np + 1], pfh[kc], vbl + 2);
            }
        }
    }

    // ---- epilogue: O as f16 hi/lo split [b][c][l] ----
    float i0 = 1.0f / l0, i1 = 1.0f / l1;
    int q0 = qt * 128 + w * 16 + (lane >> 2);
    #pragma unroll
    for (int nt = 0; nt < 4; nt++) {
        int c = n * 32 + nt * 8 + (lane & 3) * 2;
        float v00 = oacc[nt][0] * i0, v01 = oacc[nt][1] * i0;
        float v10 = oacc[nt][2] * i1, v11 = oacc[nt][3] * i1;
        size_t b0 = ((size_t)(b * 256 + c)) * L_DIM + q0;
        size_t b1 = b0 + L_DIM;
        __half h;
        h = __float2half_rn(v00); g_xth[b0] = h;     g_xtl[b0] = __float2half_rn(v00 - __half2float(h));
        h = __float2half_rn(v01); g_xth[b1] = h;     g_xtl[b1] = __float2half_rn(v01 - __half2float(h));
        h = __float2half_rn(v10); g_xth[b0 + 8] = h; g_xtl[b0 + 8] = __float2half_rn(v10 - __half2float(h));
        h = __float2half_rn(v11); g_xth[b1 + 8] = h; g_xtl[b1 + 8] = __float2half_rn(v11 - __half2float(h));
    }
}

// ------------------- mma output projection: out[b][o][l] -------------------
__global__ void __launch_bounds__(256)
proj_o_mma_kernel(const float* __restrict__ bo, float* __restrict__ out)
{
    __shared__ __align__(16) __half ash[2][128 * 40];
    __shared__ __align__(16) __half bsh[2][32 * 136];
    __shared__ float bias_s[128];

    const int tid = threadIdx.x, lane = tid & 31, w = tid >> 5;
    const int lt = blockIdx.x >> 1, oh = blockIdx.x & 1;
    const int b = blockIdx.z;

    if (tid < 128) bias_s[tid] = bo[oh * 128 + tid];

    float acc[16][4] = {};
    const int rr = lane & 15;
    const int chi = (lane & 16) ? 8 : 0;

    for (int kc0 = 0; kc0 < C_DIM; kc0 += 32) {
        __syncthreads();
        #pragma unroll
        for (int i = 0; i < 2; i++) {
            int u = tid + i * 256;
            int row = u >> 2, seg = u & 3;
            int g = (oh * 128 + row) * C_DIM + kc0 + seg * 8;
            *(uint4*)&ash[0][row * 40 + seg * 8] = *(const uint4*)&g_woh[g];
            *(uint4*)&ash[1][row * 40 + seg * 8] = *(const uint4*)&g_wol[g];
        }
        #pragma unroll
        for (int i = 0; i < 2; i++) {
            int u = tid + i * 256;
            int row = u >> 4, seg = u & 15;
            size_t g = ((size_t)(b * 256 + kc0 + row)) * L_DIM + lt * 128 + seg * 8;
            *(uint4*)&bsh[0][row * 136 + seg * 8] = *(const uint4*)&g_xth[g];
            *(uint4*)&bsh[1][row * 136 + seg * 8] = *(const uint4*)&g_xtl[g];
        }
        __syncthreads();

        uint32_t af[2][2][4];
        #pragma unroll
        for (int hl = 0; hl < 2; hl++)
            #pragma unroll
            for (int kc = 0; kc < 2; kc++)
                ldsm_x4(af[hl][kc], smem_u32(&ash[hl][(w * 16 + rr) * 40 + kc * 16 + chi]));

        #pragma unroll
        for (int nt = 0; nt < 16; nt += 2) {
            #pragma unroll
            for (int kc = 0; kc < 2; kc++) {
                uint32_t bh[4], bl[4];
                ldsm_x4t(bh, smem_u32(&bsh[0][(kc * 16 + rr) * 136 + nt * 8 + chi]));
                ldsm_x4t(bl, smem_u32(&bsh[1][(kc * 16 + rr) * 136 + nt * 8 + chi]));
                mma16816(acc[nt],     af[0][kc], bh);
                mma16816(acc[nt + 1], af[0][kc], bh + 2);
                mma16816(acc[nt],     af[0][kc], bl);
                mma16816(acc[nt + 1], af[0][kc], bl + 2);
                mma16816(acc[nt],     af[1][kc], bh);
                mma16816(acc[nt + 1], af[1][kc], bh + 2);
            }
        }
    }

    const int orow = oh * 128 + w * 16 + (lane >> 2);
    const float bb0 = bias_s[w * 16 + (lane >> 2)];
    const float bb1 = bias_s[w * 16 + (lane >> 2) + 8];
    #pragma unroll
    for (int nt = 0; nt < 16; nt++) {
        int lcol = lt * 128 + nt * 8 + (lane & 3) * 2;
        float2 y0, y1;
        y0.x = acc[nt][0] + bb0; y0.y = acc[nt][1] + bb0;
        y1.x = acc[nt][2] + bb1; y1.y = acc[nt][3] + bb1;
        *(float2*)&out[((size_t)(b * 256 + orow)) * L_DIM + lcol] = y0;
        *(float2*)&out[((size_t)(b * 256 + orow + 8)) * L_DIM + lcol] = y1;
    }
}

// ---------------------------------------------------------------------------
extern "C" void kernel_launch(void* const* d_in, const int* in_sizes, int n_in,
                              void* d_out, int out_size)
{
    const float* x  = (const float*)d_in[0];
    const float* wq = (const float*)d_in[1];
    const float* bq = (const float*)d_in[2];
    const float* wk = (const float*)d_in[3];
    const float* bk = (const float*)d_in[4];
    const float* wv = (const float*)d_in[5];
    const float* bv = (const float*)d_in[6];
    const float* wo = (const float*)d_in[7];
    const float* bo = (const float*)d_in[8];
    float* out = (float*)d_out;

    split_w_kernel<<<dim3(8, 8, 3), dim3(32, 8)>>>(wq, wk, wv);
    split_wo_kernel<<<128, 256>>>(wo);
    convert_x_kernel<<<dim3(32, 8, 16), dim3(32, 8)>>>(x);
    proj_qkv_mma_kernel<<<dim3(16, 3, 16), 256>>>(bq, bk, bv);
    convert_kt_kernel<<<dim3(32, 8, 16), dim3(32, 8)>>>();
    attn_mma_kernel<<<dim3(8, 8, 16), 256>>>();
    proj_o_mma_kernel<<<dim3(16, 1, 16), 256>>>(bo, out);
}

// round 10
// speedup vs baseline: 3.3327x; 1.0258x over previous
#include <cuda_runtime.h>
#include <cuda_fp16.h>
#include <cstdint>

#define C_DIM 256
#define L_DIM 1024
#define B_DIM 16
#define NH 8
#define DH 32
#define SCALE 0.17677669529663687f
#define LOG2E 1.4426950408889634f

// f16 hi/lo split buffers
__device__ __half g_qh[B_DIM * L_DIM * C_DIM];   // [b][l][c]
__device__ __half g_ql[B_DIM * L_DIM * C_DIM];
__device__ __half g_kth[B_DIM * L_DIM * C_DIM];  // k [b][l][c]
__device__ __half g_ktl[B_DIM * L_DIM * C_DIM];
__device__ __half g_kh2[B_DIM * C_DIM * L_DIM];  // k [b][c][l]
__device__ __half g_kl2[B_DIM * C_DIM * L_DIM];
__device__ __half g_vth[B_DIM * L_DIM * C_DIM];  // v [b][l][c]
__device__ __half g_vtl[B_DIM * L_DIM * C_DIM];
__device__ __half g_xth[B_DIM * L_DIM * C_DIM];  // x^T split; reused as att split [b][c][l]
__device__ __half g_xtl[B_DIM * L_DIM * C_DIM];
__device__ __half g_wh[3 * C_DIM * C_DIM];       // W^T [sel][c][o]
__device__ __half g_wl[3 * C_DIM * C_DIM];
__device__ __half g_woh[C_DIM * C_DIM];          // Wo [o][c]
__device__ __half g_wol[C_DIM * C_DIM];

__device__ __forceinline__ float ex2f(float x) {
    float r; asm("ex2.approx.f32 %0, %1;" : "=f"(r) : "f"(x)); return r;
}
__device__ __forceinline__ uint32_t smem_u32(const void* p) {
    uint32_t a;
    asm("{ .reg .u64 t; cvta.to.shared.u64 t, %1; cvt.u32.u64 %0, t; }" : "=r"(a) : "l"(p));
    return a;
}
__device__ __forceinline__ uint32_t pack_h2(float lo, float hi) {
    uint32_t r; asm("cvt.rn.f16x2.f32 %0, %1, %2;" : "=r"(r) : "f"(hi), "f"(lo)); return r;
}
__device__ __forceinline__ void ldsm_x4(uint32_t* r, uint32_t a) {
    asm volatile("ldmatrix.sync.aligned.m8n8.x4.shared.b16 {%0,%1,%2,%3}, [%4];"
        : "=r"(r[0]), "=r"(r[1]), "=r"(r[2]), "=r"(r[3]) : "r"(a));
}
__device__ __forceinline__ void ldsm_x4t(uint32_t* r, uint32_t a) {
    asm volatile("ldmatrix.sync.aligned.m8n8.x4.trans.shared.b16 {%0,%1,%2,%3}, [%4];"
        : "=r"(r[0]), "=r"(r[1]), "=r"(r[2]), "=r"(r[3]) : "r"(a));
}
__device__ __forceinline__ void mma16816(float* d, const uint32_t* a, const uint32_t* b) {
    asm volatile("mma.sync.aligned.m16n8k16.row.col.f32.f16.f16.f32 "
        "{%0,%1,%2,%3}, {%4,%5,%6,%7}, {%8,%9}, {%0,%1,%2,%3};"
        : "+f"(d[0]), "+f"(d[1]), "+f"(d[2]), "+f"(d[3])
        : "r"(a[0]), "r"(a[1]), "r"(a[2]), "r"(a[3]), "r"(b[0]), "r"(b[1]));
}
__device__ __forceinline__ float shflx(float v, int m) {
    return __shfl_xor_sync(0xffffffffu, v, m);
}
__device__ __forceinline__ void cpa16(uint32_t s, const void* g) {
    asm volatile("cp.async.cg.shared.global [%0], [%1], 16;" :: "r"(s), "l"(g));
}
#define CP_COMMIT() asm volatile("cp.async.commit_group;" ::: "memory")
#define CP_WAIT0()  asm volatile("cp.async.wait_group 0;" ::: "memory")

// ------------------- prep kernels -------------------
__global__ void __launch_bounds__(256)
split_w_kernel(const float* __restrict__ wq, const float* __restrict__ wk, const float* __restrict__ wv)
{
    __shared__ float t[32][33];
    const int sel = blockIdx.z;
    const float* W = (sel == 0) ? wq : (sel == 1) ? wk : wv;
    __half* dh = g_wh + sel * C_DIM * C_DIM;
    __half* dl = g_wl + sel * C_DIM * C_DIM;
    const int o0 = blockIdx.x * 32, c0 = blockIdx.y * 32;
    const int tx = threadIdx.x, ty = threadIdx.y;
    #pragma unroll
    for (int i = 0; i < 4; i++)
        t[ty + 8 * i][tx] = W[(o0 + ty + 8 * i) * C_DIM + c0 + tx];
    __syncthreads();
    #pragma unroll
    for (int i = 0; i < 4; i++) {
        float v = t[tx][ty + 8 * i];
        __half h = __float2half_rn(v);
        int o = (c0 + ty + 8 * i) * C_DIM + o0 + tx;
        dh[o] = h;
        dl[o] = __float2half_rn(v - __half2float(h));
    }
}

__global__ void __launch_bounds__(256)
split_wo_kernel(const float* __restrict__ wo)
{
    int i = blockIdx.x * 256 + threadIdx.x;
    const float2 v = ((const float2*)wo)[i];
    __half2 h = __floats2half2_rn(v.x, v.y);
    float2 hf = __half22float2(h);
    ((__half2*)g_woh)[i] = h;
    ((__half2*)g_wol)[i] = __floats2half2_rn(v.x - hf.x, v.y - hf.y);
}

__global__ void __launch_bounds__(256)
convert_x_kernel(const float* __restrict__ x)
{
    __shared__ float t[32][33];
    const int b = blockIdx.z;
    const float* src = x + (size_t)b * C_DIM * L_DIM;
    __half* dh = g_xth + (size_t)b * L_DIM * C_DIM;
    __half* dl = g_xtl + (size_t)b * L_DIM * C_DIM;
    const int l0 = blockIdx.x * 32, c0 = blockIdx.y * 32;
    const int tx = threadIdx.x, ty = threadIdx.y;
    #pragma unroll
    for (int i = 0; i < 4; i++)
        t[ty + 8 * i][tx] = src[(size_t)(c0 + ty + 8 * i) * L_DIM + l0 + tx];
    __syncthreads();
    #pragma unroll
    for (int i = 0; i < 4; i++) {
        float v = t[tx][ty + 8 * i];
        __half h = __float2half_rn(v);
        size_t o = (size_t)(l0 + ty + 8 * i) * C_DIM + c0 + tx;
        dh[o] = h;
        dl[o] = __float2half_rn(v - __half2float(h));
    }
}

// ------------------- mma QKV projection: cp.async double-buffered -------------------
// dyn smem stage (halves): AH 0 (5120), AL 5120, BH 10240 (4352), BL 14592; stage = 18944
#define PJ_STAGE 18944
#define PJ_BYTES (2 * PJ_STAGE * 2)

__global__ void __launch_bounds__(256)
proj_qkv_mma_kernel(const float* __restrict__ bq, const float* __restrict__ bk,
                    const float* __restrict__ bv)
{
    extern __shared__ __half dynsm[];
    __shared__ float bias_s[128];

    const int tid = threadIdx.x, lane = tid & 31, w = tid >> 5;
    const int lt = blockIdx.x >> 1, oh = blockIdx.x & 1;
    const int sel = blockIdx.y, b = blockIdx.z;

    const __half* xh = g_xth + (size_t)b * L_DIM * C_DIM;
    const __half* xl = g_xtl + (size_t)b * L_DIM * C_DIM;
    const __half* wh = g_wh + sel * C_DIM * C_DIM;
    const __half* wl = g_wl + sel * C_DIM * C_DIM;
    const float* bias = (sel == 0) ? bq : (sel == 1) ? bk : bv;
    __half* Yh = (sel == 0) ? g_qh : (sel == 1) ? g_kth : g_vth;
    __half* Yl = (sel == 0) ? g_ql : (sel == 1) ? g_ktl : g_vtl;
    const float sc = (sel == 0) ? (SCALE * LOG2E) : 1.0f;

    if (tid < 128) bias_s[tid] = bias[oh * 128 + tid];

    const int arow = tid >> 2, aseg = tid & 3;       // A: +256 -> +64 rows
    const int brow = tid >> 4, bseg = tid & 15;      // B: +256 -> +16 rows

    // prologue: stage 0
    {
        __half* base = dynsm;
        #pragma unroll
        for (int i = 0; i < 2; i++) {
            int row = arow + i * 64;
            size_t g = (size_t)(lt * 128 + row) * C_DIM + aseg * 8;
            cpa16(smem_u32(base + row * 40 + aseg * 8), &xh[g]);
            cpa16(smem_u32(base + 5120 + row * 40 + aseg * 8), &xl[g]);
        }
        #pragma unroll
        for (int i = 0; i < 2; i++) {
            int row = brow + i * 16;
            int g = row * C_DIM + oh * 128 + bseg * 8;
            cpa16(smem_u32(base + 10240 + row * 136 + bseg * 8), &wh[g]);
            cpa16(smem_u32(base + 14592 + row * 136 + bseg * 8), &wl[g]);
        }
        CP_COMMIT();
    }

    float acc[16][4] = {};
    const int rr = lane & 15;
    const int chi = (lane & 16) ? 8 : 0;

    for (int it = 0; it < 8; it++) {
        CP_WAIT0();
        __syncthreads();

        if (it < 7) {
            __half* base = dynsm + ((it + 1) & 1) * PJ_STAGE;
            int kc0 = (it + 1) * 32;
            #pragma unroll
            for (int i = 0; i < 2; i++) {
                int row = arow + i * 64;
                size_t g = (size_t)(lt * 128 + row) * C_DIM + kc0 + aseg * 8;
                cpa16(smem_u32(base + row * 40 + aseg * 8), &xh[g]);
                cpa16(smem_u32(base + 5120 + row * 40 + aseg * 8), &xl[g]);
            }
            #pragma unroll
            for (int i = 0; i < 2; i++) {
                int row = brow + i * 16;
                int g = (kc0 + row) * C_DIM + oh * 128 + bseg * 8;
                cpa16(smem_u32(base + 10240 + row * 136 + bseg * 8), &wh[g]);
                cpa16(smem_u32(base + 14592 + row * 136 + bseg * 8), &wl[g]);
            }
            CP_COMMIT();
        }

        __half* cur = dynsm + (it & 1) * PJ_STAGE;
        __half* ah = cur;
        __half* al = cur + 5120;
        __half* bh_s = cur + 10240;
        __half* bl_s = cur + 14592;

        uint32_t af[2][2][4];
        #pragma unroll
        for (int kc = 0; kc < 2; kc++) {
            ldsm_x4(af[0][kc], smem_u32(&ah[(w * 16 + rr) * 40 + kc * 16 + chi]));
            ldsm_x4(af[1][kc], smem_u32(&al[(w * 16 + rr) * 40 + kc * 16 + chi]));
        }

        #pragma unroll
        for (int nt = 0; nt < 16; nt += 2) {
            #pragma unroll
            for (int kc = 0; kc < 2; kc++) {
                uint32_t bh[4], bl[4];
                ldsm_x4t(bh, smem_u32(&bh_s[(kc * 16 + rr) * 136 + nt * 8 + chi]));
                ldsm_x4t(bl, smem_u32(&bl_s[(kc * 16 + rr) * 136 + nt * 8 + chi]));
                mma16816(acc[nt],     af[0][kc], bh);
                mma16816(acc[nt + 1], af[0][kc], bh + 2);
                mma16816(acc[nt],     af[0][kc], bl);
                mma16816(acc[nt + 1], af[0][kc], bl + 2);
                mma16816(acc[nt],     af[1][kc], bh);
                mma16816(acc[nt + 1], af[1][kc], bh + 2);
            }
        }
    }

    // epilogue: write f16 hi/lo split directly, [b][l][c]
    const int r0 = lt * 128 + w * 16 + (lane >> 2);
    #pragma unroll
    for (int nt = 0; nt < 16; nt++) {
        int c0 = nt * 8 + (lane & 3) * 2;
        float b0 = bias_s[c0], b1 = bias_s[c0 + 1];
        float v0 = (acc[nt][0] + b0) * sc, v1 = (acc[nt][1] + b1) * sc;
        float v2 = (acc[nt][2] + b0) * sc, v3 = (acc[nt][3] + b1) * sc;
        __half2 h0 = __floats2half2_rn(v0, v1);
        __half2 h1 = __floats2half2_rn(v2, v3);
        float2 f0 = __half22float2(h0);
        float2 f1 = __half22float2(h1);
        size_t o0 = (size_t)(b * 1024 + r0) * C_DIM + oh * 128 + c0;
        size_t o1 = (size_t)(b * 1024 + r0 + 8) * C_DIM + oh * 128 + c0;
        *(__half2*)&Yh[o0] = h0;
        *(__half2*)&Yh[o1] = h1;
        *(__half2*)&Yl[o0] = __floats2half2_rn(v0 - f0.x, v1 - f0.y);
        *(__half2*)&Yl[o1] = __floats2half2_rn(v2 - f1.x, v3 - f1.y);
    }
}

// ------------------- k transpose (half -> half) -------------------
__global__ void __launch_bounds__(256)
convert_kt_kernel()
{
    __shared__ __half th[32][34];
    __shared__ __half tl[32][34];
    const int b = blockIdx.z;
    const int l0 = blockIdx.x * 32, c0 = blockIdx.y * 32;
    const int tx = threadIdx.x, ty = threadIdx.y;
    #pragma unroll
    for (int i = 0; i < 4; i++) {
        size_t g = (size_t)(b * 1024 + l0 + ty + 8 * i) * C_DIM + c0 + tx;
        th[ty + 8 * i][tx] = g_kth[g];
        tl[ty + 8 * i][tx] = g_ktl[g];
    }
    __syncthreads();
    #pragma unroll
    for (int i = 0; i < 4; i++) {
        size_t o = (size_t)(b * 256 + c0 + ty + 8 * i) * L_DIM + l0 + tx;
        g_kh2[o] = th[tx][ty + 8 * i];
        g_kl2[o] = tl[tx][ty + 8 * i];
    }
}

// ------------------- flash attention (unchanged from R9 win) -------------------
__global__ void __launch_bounds__(256, 2)
attn_mma_kernel()
{
    __shared__ __align__(16) __half pool[10240 + 9728];

    const int tid = threadIdx.x, lane = tid & 31, w = tid >> 5;
    const int qt = blockIdx.x, n = blockIdx.y, b = blockIdx.z;
    const int rr = lane & 15;
    const int hoff = (lane & 16) ? 8 : 0;

    {
        __half* base = pool + 10240;
        int row = tid >> 3, seg = tid & 7;
        size_t gk = ((size_t)(b * 256 + n * 32 + row)) * L_DIM + seg * 8;
        cpa16(smem_u32(base + row * 72 + seg * 8), &g_kh2[gk]);
        cpa16(smem_u32(base + 2304 + row * 72 + seg * 8), &g_kl2[gk]);
        int vrow = tid >> 2, vseg = tid & 3;
        size_t gv = ((size_t)(b * 1024 + vrow)) * C_DIM + n * 32 + vseg * 8;
        cpa16(smem_u32(base + 4608 + vrow * 40 + vseg * 8), &g_vth[gv]);
        cpa16(smem_u32(base + 7168 + vrow * 40 + vseg * 8), &g_vtl[gv]);
        CP_COMMIT();
    }

    for (int u = tid; u < 512; u += 256) {
        int row = u >> 2, seg = u & 3;
        size_t g = ((size_t)(b * 1024 + qt * 128 + row)) * C_DIM + n * 32 + seg * 8;
        *(uint4*)&pool[row * 40 + seg * 8] = *(const uint4*)&g_qh[g];
        *(uint4*)&pool[5120 + row * 40 + seg * 8] = *(const uint4*)&g_ql[g];
    }
    __syncthreads();

    uint32_t qf[2][2][4];
    #pragma unroll
    for (int hl = 0; hl < 2; hl++)
        #pragma unroll
        for (int kc = 0; kc < 2; kc++)
            ldsm_x4(qf[hl][kc], smem_u32(&pool[hl * 5120 + (w * 16 + rr) * 40 + kc * 16 + hoff]));
    __syncthreads();

    float oacc[4][4] = {};
    float m0 = -1e30f, m1 = -1e30f, l0 = 0.0f, l1 = 0.0f;

    for (int t = 0; t < 16; t++) {
        CP_WAIT0();
        __syncthreads();

        if (t < 15) {
            __half* base = pool + (((t + 1) & 1) ? 0 : 10240);
            int row = tid >> 3, seg = tid & 7;
            size_t gk = ((size_t)(b * 256 + n * 32 + row)) * L_DIM + (t + 1) * 64 + seg * 8;
            cpa16(smem_u32(base + row * 72 + seg * 8), &g_kh2[gk]);
            cpa16(smem_u32(base + 2304 + row * 72 + seg * 8), &g_kl2[gk]);
            int vrow = tid >> 2, vseg = tid & 3;
            size_t gv = ((size_t)(b * 1024 + (t + 1) * 64 + vrow)) * C_DIM + n * 32 + vseg * 8;
            cpa16(smem_u32(base + 4608 + vrow * 40 + vseg * 8), &g_vth[gv]);
            cpa16(smem_u32(base + 7168 + vrow * 40 + vseg * 8), &g_vtl[gv]);
            CP_COMMIT();
        }

        __half* cur = pool + ((t & 1) ? 0 : 10240);
        __half* ksh0 = cur;
        __half* ksh1 = cur + 2304;
        __half* vsh0 = cur + 4608;
        __half* vsh1 = cur + 7168;

        float sacc[8][4];
        #pragma unroll
        for (int nt = 0; nt < 8; nt += 2) {
            sacc[nt][0] = sacc[nt][1] = sacc[nt][2] = sacc[nt][3] = 0.0f;
            sacc[nt+1][0] = sacc[nt+1][1] = sacc[nt+1][2] = sacc[nt+1][3] = 0.0f;
            #pragma unroll
            for (int kc = 0; kc < 2; kc++) {
                uint32_t kbh[4], kbl[4];
                ldsm_x4t(kbh, smem_u32(&ksh0[(kc * 16 + rr) * 72 + nt * 8 + hoff]));
                ldsm_x4t(kbl, smem_u32(&ksh1[(kc * 16 + rr) * 72 + nt * 8 + hoff]));
                mma16816(sacc[nt],     qf[0][kc], kbh);
                mma16816(sacc[nt + 1], qf[0][kc], kbh + 2);
                mma16816(sacc[nt],     qf[0][kc], kbl);
                mma16816(sacc[nt + 1], qf[0][kc], kbl + 2);
                mma16816(sacc[nt],     qf[1][kc], kbh);
                mma16816(sacc[nt + 1], qf[1][kc], kbh + 2);
            }
        }

        float mt0 = -1e30f, mt1 = -1e30f;
        #pragma unroll
        for (int nt = 0; nt < 8; nt++) {
            mt0 = fmaxf(mt0, fmaxf(sacc[nt][0], sacc[nt][1]));
            mt1 = fmaxf(mt1, fmaxf(sacc[nt][2], sacc[nt][3]));
        }
        mt0 = fmaxf(mt0, shflx(mt0, 1)); mt0 = fmaxf(mt0, shflx(mt0, 2));
        mt1 = fmaxf(mt1, shflx(mt1, 1)); mt1 = fmaxf(mt1, shflx(mt1, 2));
        float nm0 = fmaxf(m0, mt0), nm1 = fmaxf(m1, mt1);
        float c0 = ex2f(m0 - nm0), c1 = ex2f(m1 - nm1);
        m0 = nm0; m1 = nm1;
        l0 *= c0; l1 *= c1;
        #pragma unroll
        for (int nt = 0; nt < 4; nt++) {
            oacc[nt][0] *= c0; oacc[nt][1] *= c0;
            oacc[nt][2] *= c1; oacc[nt][3] *= c1;
        }
        float rs0 = 0.0f, rs1 = 0.0f;
        #pragma unroll
        for (int nt = 0; nt < 8; nt++) {
            sacc[nt][0] = ex2f(sacc[nt][0] - m0);
            sacc[nt][1] = ex2f(sacc[nt][1] - m0);
            sacc[nt][2] = ex2f(sacc[nt][2] - m1);
            sacc[nt][3] = ex2f(sacc[nt][3] - m1);
            rs0 += sacc[nt][0] + sacc[nt][1];
            rs1 += sacc[nt][2] + sacc[nt][3];
        }
        rs0 += shflx(rs0, 1); rs0 += shflx(rs0, 2);
        rs1 += shflx(rs1, 1); rs1 += shflx(rs1, 2);
        l0 += rs0; l1 += rs1;

        uint32_t pfh[4][4];
        #pragma unroll
        for (int kc = 0; kc < 4; kc++) {
            const float* s0 = sacc[2 * kc];
            const float* s1 = sacc[2 * kc + 1];
            pfh[kc][0] = pack_h2(s0[0], s0[1]);
            pfh[kc][1] = pack_h2(s0[2], s0[3]);
            pfh[kc][2] = pack_h2(s1[0], s1[1]);
            pfh[kc][3] = pack_h2(s1[2], s1[3]);
        }

        #pragma unroll
        for (int kc = 0; kc < 4; kc++) {
            #pragma unroll
            for (int np = 0; np < 2; np++) {
                uint32_t vbh[4], vbl[4];
                ldsm_x4t(vbh, smem_u32(&vsh0[(kc * 16 + rr) * 40 + np * 16 + hoff]));
                ldsm_x4t(vbl, smem_u32(&vsh1[(kc * 16 + rr) * 40 + np * 16 + hoff]));
                mma16816(oacc[2 * np],     pfh[kc], vbh);
                mma16816(oacc[2 * np + 1], pfh[kc], vbh + 2);
                mma16816(oacc[2 * np],     pfh[kc], vbl);
                mma16816(oacc[2 * np + 1], pfh[kc], vbl + 2);
            }
        }
    }

    float i0 = 1.0f / l0, i1 = 1.0f / l1;
    int q0 = qt * 128 + w * 16 + (lane >> 2);
    #pragma unroll
    for (int nt = 0; nt < 4; nt++) {
        int c = n * 32 + nt * 8 + (lane & 3) * 2;
        float v00 = oacc[nt][0] * i0, v01 = oacc[nt][1] * i0;
        float v10 = oacc[nt][2] * i1, v11 = oacc[nt][3] * i1;
        size_t b0 = ((size_t)(b * 256 + c)) * L_DIM + q0;
        size_t b1 = b0 + L_DIM;
        __half h;
        h = __float2half_rn(v00); g_xth[b0] = h;     g_xtl[b0] = __float2half_rn(v00 - __half2float(h));
        h = __float2half_rn(v01); g_xth[b1] = h;     g_xtl[b1] = __float2half_rn(v01 - __half2float(h));
        h = __float2half_rn(v10); g_xth[b0 + 8] = h; g_xtl[b0 + 8] = __float2half_rn(v10 - __half2float(h));
        h = __float2half_rn(v11); g_xth[b1 + 8] = h; g_xtl[b1 + 8] = __float2half_rn(v11 - __half2float(h));
    }
}

// ------------------- mma output projection: cp.async double-buffered -------------------
__global__ void __launch_bounds__(256)
proj_o_mma_kernel(const float* __restrict__ bo, float* __restrict__ out)
{
    extern __shared__ __half dynsm[];
    __shared__ float bias_s[128];

    const int tid = threadIdx.x, lane = tid & 31, w = tid >> 5;
    const int lt = blockIdx.x >> 1, oh = blockIdx.x & 1;
    const int b = blockIdx.z;

    if (tid < 128) bias_s[tid] = bo[oh * 128 + tid];

    const int arow = tid >> 2, aseg = tid & 3;
    const int brow = tid >> 4, bseg = tid & 15;

    {
        __half* base = dynsm;
        #pragma unroll
        for (int i = 0; i < 2; i++) {
            int row = arow + i * 64;
            int g = (oh * 128 + row) * C_DIM + aseg * 8;
            cpa16(smem_u32(base + row * 40 + aseg * 8), &g_woh[g]);
            cpa16(smem_u32(base + 5120 + row * 40 + aseg * 8), &g_wol[g]);
        }
        #pragma unroll
        for (int i = 0; i < 2; i++) {
            int row = brow + i * 16;
            size_t g = ((size_t)(b * 256 + row)) * L_DIM + lt * 128 + bseg * 8;
            cpa16(smem_u32(base + 10240 + row * 136 + bseg * 8), &g_xth[g]);
            cpa16(smem_u32(base + 14592 + row * 136 + bseg * 8), &g_xtl[g]);
        }
        CP_COMMIT();
    }

    float acc[16][4] = {};
    const int rr = lane & 15;
    const int chi = (lane & 16) ? 8 : 0;

    for (int it = 0; it < 8; it++) {
        CP_WAIT0();
        __syncthreads();

        if (it < 7) {
            __half* base = dynsm + ((it + 1) & 1) * PJ_STAGE;
            int kc0 = (it + 1) * 32;
            #pragma unroll
            for (int i = 0; i < 2; i++) {
                int row = arow + i * 64;
                int g = (oh * 128 + row) * C_DIM + kc0 + aseg * 8;
                cpa16(smem_u32(base + row * 40 + aseg * 8), &g_woh[g]);
                cpa16(smem_u32(base + 5120 + row * 40 + aseg * 8), &g_wol[g]);
            }
            #pragma unroll
            for (int i = 0; i < 2; i++) {
                int row = brow + i * 16;
                size_t g = ((size_t)(b * 256 + kc0 + row)) * L_DIM + lt * 128 + bseg * 8;
                cpa16(smem_u32(base + 10240 + row * 136 + bseg * 8), &g_xth[g]);
                cpa16(smem_u32(base + 14592 + row * 136 + bseg * 8), &g_xtl[g]);
            }
            CP_COMMIT();
        }

        __half* cur = dynsm + (it & 1) * PJ_STAGE;
        __half* ah = cur;
        __half* al = cur + 5120;
        __half* bh_s = cur + 10240;
        __half* bl_s = cur + 14592;

        uint32_t af[2][2][4];
        #pragma unroll
        for (int kc = 0; kc < 2; kc++) {
            ldsm_x4(af[0][kc], smem_u32(&ah[(w * 16 + rr) * 40 + kc * 16 + chi]));
            ldsm_x4(af[1][kc], smem_u32(&al[(w * 16 + rr) * 40 + kc * 16 + chi]));
        }

        #pragma unroll
        for (int nt = 0; nt < 16; nt += 2) {
            #pragma unroll
            for (int kc = 0; kc < 2; kc++) {
                uint32_t bh[4], bl[4];
                ldsm_x4t(bh, smem_u32(&bh_s[(kc * 16 + rr) * 136 + nt * 8 + chi]));
                ldsm_x4t(bl, smem_u32(&bl_s[(kc * 16 + rr) * 136 + nt * 8 + chi]));
                mma16816(acc[nt],     af[0][kc], bh);
                mma16816(acc[nt + 1], af[0][kc], bh + 2);
                mma16816(acc[nt],     af[0][kc], bl);
                mma16816(acc[nt + 1], af[0][kc], bl + 2);
                mma16816(acc[nt],     af[1][kc], bh);
                mma16816(acc[nt + 1], af[1][kc], bh + 2);
            }
        }
    }

    const int orow = oh * 128 + w * 16 + (lane >> 2);
    const float bb0 = bias_s[w * 16 + (lane >> 2)];
    const float bb1 = bias_s[w * 16 + (lane >> 2) + 8];
    #pragma unroll
    for (int nt = 0; nt < 16; nt++) {
        int lcol = lt * 128 + nt * 8 + (lane & 3) * 2;
        float2 y0, y1;
        y0.x = acc[nt][0] + bb0; y0.y = acc[nt][1] + bb0;
        y1.x = acc[nt][2] + bb1; y1.y = acc[nt][3] + bb1;
        *(float2*)&out[((size_t)(b * 256 + orow)) * L_DIM + lcol] = y0;
        *(float2*)&out[((size_t)(b * 256 + orow + 8)) * L_DIM + lcol] = y1;
    }
}

// ---------------------------------------------------------------------------
extern "C" void kernel_launch(void* const* d_in, const int* in_sizes, int n_in,
                              void* d_out, int out_size)
{
    const float* x  = (const float*)d_in[0];
    const float* wq = (const float*)d_in[1];
    const float* bq = (const float*)d_in[2];
    const float* wk = (const float*)d_in[3];
    const float* bk = (const float*)d_in[4];
    const float* wv = (const float*)d_in[5];
    const float* bv = (const float*)d_in[6];
    const float* wo = (const float*)d_in[7];
    const float* bo = (const float*)d_in[8];
    float* out = (float*)d_out;

    cudaFuncSetAttribute(proj_qkv_mma_kernel, cudaFuncAttributeMaxDynamicSharedMemorySize, PJ_BYTES);
    cudaFuncSetAttribute(proj_o_mma_kernel, cudaFuncAttributeMaxDynamicSharedMemorySize, PJ_BYTES);

    split_w_kernel<<<dim3(8, 8, 3), dim3(32, 8)>>>(wq, wk, wv);
    split_wo_kernel<<<128, 256>>>(wo);
    convert_x_kernel<<<dim3(32, 8, 16), dim3(32, 8)>>>(x);
    proj_qkv_mma_kernel<<<dim3(16, 3, 16), 256, PJ_BYTES>>>(bq, bk, bv);
    convert_kt_kernel<<<dim3(32, 8, 16), dim3(32, 8)>>>();
    attn_mma_kernel<<<dim3(8, 8, 16), 256>>>();
    proj_o_mma_kernel<<<dim3(16, 1, 16), 256, PJ_BYTES>>>(bo, out);
}

// round 11
// speedup vs baseline: 3.5268x; 1.0583x over previous
#include <cuda_runtime.h>
#include <cuda_fp16.h>
#include <cstdint>

#define C_DIM 256
#define L_DIM 1024
#define B_DIM 16
#define NH 8
#define DH 32
#define SCALE 0.17677669529663687f
#define LOG2E 1.4426950408889634f

// f16 hi/lo split buffers
__device__ __half g_qh[B_DIM * L_DIM * C_DIM];   // [b][l][c]
__device__ __half g_kth[B_DIM * L_DIM * C_DIM];  // k [b][l][c]
__device__ __half g_ktl[B_DIM * L_DIM * C_DIM];
__device__ __half g_vth[B_DIM * L_DIM * C_DIM];  // v [b][l][c]
__device__ __half g_vtl[B_DIM * L_DIM * C_DIM];
__device__ __half g_xth[B_DIM * L_DIM * C_DIM];  // x^T split; reused as att split [b][c][l]
__device__ __half g_xtl[B_DIM * L_DIM * C_DIM];
__device__ __half g_wh[3 * C_DIM * C_DIM];       // W^T [sel][c][o]
__device__ __half g_wl[3 * C_DIM * C_DIM];
__device__ __half g_woh[C_DIM * C_DIM];          // Wo [o][c]
__device__ __half g_wol[C_DIM * C_DIM];

__device__ __forceinline__ float ex2f(float x) {
    float r; asm("ex2.approx.f32 %0, %1;" : "=f"(r) : "f"(x)); return r;
}
__device__ __forceinline__ uint32_t smem_u32(const void* p) {
    uint32_t a;
    asm("{ .reg .u64 t; cvta.to.shared.u64 t, %1; cvt.u32.u64 %0, t; }" : "=r"(a) : "l"(p));
    return a;
}
__device__ __forceinline__ uint32_t pack_h2(float lo, float hi) {
    uint32_t r; asm("cvt.rn.f16x2.f32 %0, %1, %2;" : "=r"(r) : "f"(hi), "f"(lo)); return r;
}
__device__ __forceinline__ void ldsm_x4(uint32_t* r, uint32_t a) {
    asm volatile("ldmatrix.sync.aligned.m8n8.x4.shared.b16 {%0,%1,%2,%3}, [%4];"
        : "=r"(r[0]), "=r"(r[1]), "=r"(r[2]), "=r"(r[3]) : "r"(a));
}
__device__ __forceinline__ void ldsm_x4t(uint32_t* r, uint32_t a) {
    asm volatile("ldmatrix.sync.aligned.m8n8.x4.trans.shared.b16 {%0,%1,%2,%3}, [%4];"
        : "=r"(r[0]), "=r"(r[1]), "=r"(r[2]), "=r"(r[3]) : "r"(a));
}
__device__ __forceinline__ void mma16816(float* d, const uint32_t* a, const uint32_t* b) {
    asm volatile("mma.sync.aligned.m16n8k16.row.col.f32.f16.f16.f32 "
        "{%0,%1,%2,%3}, {%4,%5,%6,%7}, {%8,%9}, {%0,%1,%2,%3};"
        : "+f"(d[0]), "+f"(d[1]), "+f"(d[2]), "+f"(d[3])
        : "r"(a[0]), "r"(a[1]), "r"(a[2]), "r"(a[3]), "r"(b[0]), "r"(b[1]));
}
__device__ __forceinline__ float shflx(float v, int m) {
    return __shfl_xor_sync(0xffffffffu, v, m);
}
__device__ __forceinline__ void cpa16(uint32_t s, const void* g) {
    asm volatile("cp.async.cg.shared.global [%0], [%1], 16;" :: "r"(s), "l"(g));
}
#define CP_COMMIT() asm volatile("cp.async.commit_group;" ::: "memory")
#define CP_WAIT0()  asm volatile("cp.async.wait_group 0;" ::: "memory")

// ------------------- prep kernels -------------------
__global__ void __launch_bounds__(256)
split_w_kernel(const float* __restrict__ wq, const float* __restrict__ wk, const float* __restrict__ wv)
{
    __shared__ float t[32][33];
    const int sel = blockIdx.z;
    const float* W = (sel == 0) ? wq : (sel == 1) ? wk : wv;
    __half* dh = g_wh + sel * C_DIM * C_DIM;
    __half* dl = g_wl + sel * C_DIM * C_DIM;
    const int o0 = blockIdx.x * 32, c0 = blockIdx.y * 32;
    const int tx = threadIdx.x, ty = threadIdx.y;
    #pragma unroll
    for (int i = 0; i < 4; i++)
        t[ty + 8 * i][tx] = W[(o0 + ty + 8 * i) * C_DIM + c0 + tx];
    __syncthreads();
    #pragma unroll
    for (int i = 0; i < 4; i++) {
        float v = t[tx][ty + 8 * i];
        __half h = __float2half_rn(v);
        int o = (c0 + ty + 8 * i) * C_DIM + o0 + tx;
        dh[o] = h;
        dl[o] = __float2half_rn(v - __half2float(h));
    }
}

__global__ void __launch_bounds__(256)
split_wo_kernel(const float* __restrict__ wo)
{
    int i = blockIdx.x * 256 + threadIdx.x;
    const float2 v = ((const float2*)wo)[i];
    __half2 h = __floats2half2_rn(v.x, v.y);
    float2 hf = __half22float2(h);
    ((__half2*)g_woh)[i] = h;
    ((__half2*)g_wol)[i] = __floats2half2_rn(v.x - hf.x, v.y - hf.y);
}

__global__ void __launch_bounds__(256)
convert_x_kernel(const float* __restrict__ x)
{
    __shared__ float t[32][33];
    const int b = blockIdx.z;
    const float* src = x + (size_t)b * C_DIM * L_DIM;
    __half* dh = g_xth + (size_t)b * L_DIM * C_DIM;
    __half* dl = g_xtl + (size_t)b * L_DIM * C_DIM;
    const int l0 = blockIdx.x * 32, c0 = blockIdx.y * 32;
    const int tx = threadIdx.x, ty = threadIdx.y;
    #pragma unroll
    for (int i = 0; i < 4; i++)
        t[ty + 8 * i][tx] = src[(size_t)(c0 + ty + 8 * i) * L_DIM + l0 + tx];
    __syncthreads();
    #pragma unroll
    for (int i = 0; i < 4; i++) {
        float v = t[tx][ty + 8 * i];
        __half h = __float2half_rn(v);
        size_t o = (size_t)(l0 + ty + 8 * i) * C_DIM + c0 + tx;
        dh[o] = h;
        dl[o] = __float2half_rn(v - __half2float(h));
    }
}

// ------------------- mma QKV projection: cp.async double-buffered -------------------
// dyn smem stage (halves): AH 0 (5120), AL 5120, BH 10240 (4352), BL 14592; stage = 18944
#define PJ_STAGE 18944
#define PJ_BYTES (2 * PJ_STAGE * 2)

__global__ void __launch_bounds__(256)
proj_qkv_mma_kernel(const float* __restrict__ bq, const float* __restrict__ bk,
                    const float* __restrict__ bv)
{
    extern __shared__ __half dynsm[];
    __shared__ float bias_s[128];

    const int tid = threadIdx.x, lane = tid & 31, w = tid >> 5;
    const int lt = blockIdx.x >> 1, oh = blockIdx.x & 1;
    const int sel = blockIdx.y, b = blockIdx.z;

    const __half* xh = g_xth + (size_t)b * L_DIM * C_DIM;
    const __half* xl = g_xtl + (size_t)b * L_DIM * C_DIM;
    const __half* wh = g_wh + sel * C_DIM * C_DIM;
    const __half* wl = g_wl + sel * C_DIM * C_DIM;
    const float* bias = (sel == 0) ? bq : (sel == 1) ? bk : bv;
    __half* Yh = (sel == 0) ? g_qh : (sel == 1) ? g_kth : g_vth;
    __half* Yl = (sel == 0) ? (__half*)0 : (sel == 1) ? g_ktl : g_vtl;  // q lo never consumed
    const float sc = (sel == 0) ? (SCALE * LOG2E) : 1.0f;

    if (tid < 128) bias_s[tid] = bias[oh * 128 + tid];

    const int arow = tid >> 2, aseg = tid & 3;
    const int brow = tid >> 4, bseg = tid & 15;

    {
        __half* base = dynsm;
        #pragma unroll
        for (int i = 0; i < 2; i++) {
            int row = arow + i * 64;
            size_t g = (size_t)(lt * 128 + row) * C_DIM + aseg * 8;
            cpa16(smem_u32(base + row * 40 + aseg * 8), &xh[g]);
            cpa16(smem_u32(base + 5120 + row * 40 + aseg * 8), &xl[g]);
        }
        #pragma unroll
        for (int i = 0; i < 2; i++) {
            int row = brow + i * 16;
            int g = row * C_DIM + oh * 128 + bseg * 8;
            cpa16(smem_u32(base + 10240 + row * 136 + bseg * 8), &wh[g]);
            cpa16(smem_u32(base + 14592 + row * 136 + bseg * 8), &wl[g]);
        }
        CP_COMMIT();
    }

    float acc[16][4] = {};
    const int rr = lane & 15;
    const int chi = (lane & 16) ? 8 : 0;

    for (int it = 0; it < 8; it++) {
        CP_WAIT0();
        __syncthreads();

        if (it < 7) {
            __half* base = dynsm + ((it + 1) & 1) * PJ_STAGE;
            int kc0 = (it + 1) * 32;
            #pragma unroll
            for (int i = 0; i < 2; i++) {
                int row = arow + i * 64;
                size_t g = (size_t)(lt * 128 + row) * C_DIM + kc0 + aseg * 8;
                cpa16(smem_u32(base + row * 40 + aseg * 8), &xh[g]);
                cpa16(smem_u32(base + 5120 + row * 40 + aseg * 8), &xl[g]);
            }
            #pragma unroll
            for (int i = 0; i < 2; i++) {
                int row = brow + i * 16;
                int g = (kc0 + row) * C_DIM + oh * 128 + bseg * 8;
                cpa16(smem_u32(base + 10240 + row * 136 + bseg * 8), &wh[g]);
                cpa16(smem_u32(base + 14592 + row * 136 + bseg * 8), &wl[g]);
            }
            CP_COMMIT();
        }

        __half* cur = dynsm + (it & 1) * PJ_STAGE;
        __half* ah = cur;
        __half* al = cur + 5120;
        __half* bh_s = cur + 10240;
        __half* bl_s = cur + 14592;

        uint32_t af[2][2][4];
        #pragma unroll
        for (int kc = 0; kc < 2; kc++) {
            ldsm_x4(af[0][kc], smem_u32(&ah[(w * 16 + rr) * 40 + kc * 16 + chi]));
            ldsm_x4(af[1][kc], smem_u32(&al[(w * 16 + rr) * 40 + kc * 16 + chi]));
        }

        #pragma unroll
        for (int nt = 0; nt < 16; nt += 2) {
            #pragma unroll
            for (int kc = 0; kc < 2; kc++) {
                uint32_t bh[4], bl[4];
                ldsm_x4t(bh, smem_u32(&bh_s[(kc * 16 + rr) * 136 + nt * 8 + chi]));
                ldsm_x4t(bl, smem_u32(&bl_s[(kc * 16 + rr) * 136 + nt * 8 + chi]));
                mma16816(acc[nt],     af[0][kc], bh);
                mma16816(acc[nt + 1], af[0][kc], bh + 2);
                mma16816(acc[nt],     af[0][kc], bl);
                mma16816(acc[nt + 1], af[0][kc], bl + 2);
                mma16816(acc[nt],     af[1][kc], bh);
                mma16816(acc[nt + 1], af[1][kc], bh + 2);
            }
        }
    }

    // epilogue: write f16 hi (and lo, except for q) in [b][l][c]
    const int r0 = lt * 128 + w * 16 + (lane >> 2);
    #pragma unroll
    for (int nt = 0; nt < 16; nt++) {
        int c0 = nt * 8 + (lane & 3) * 2;
        float b0 = bias_s[c0], b1 = bias_s[c0 + 1];
        float v0 = (acc[nt][0] + b0) * sc, v1 = (acc[nt][1] + b1) * sc;
        float v2 = (acc[nt][2] + b0) * sc, v3 = (acc[nt][3] + b1) * sc;
        __half2 h0 = __floats2half2_rn(v0, v1);
        __half2 h1 = __floats2half2_rn(v2, v3);
        size_t o0 = (size_t)(b * 1024 + r0) * C_DIM + oh * 128 + c0;
        size_t o1 = (size_t)(b * 1024 + r0 + 8) * C_DIM + oh * 128 + c0;
        *(__half2*)&Yh[o0] = h0;
        *(__half2*)&Yh[o1] = h1;
        if (sel != 0) {
            float2 f0 = __half22float2(h0);
            float2 f1 = __half22float2(h1);
            *(__half2*)&Yl[o0] = __floats2half2_rn(v0 - f0.x, v1 - f0.y);
            *(__half2*)&Yl[o1] = __floats2half2_rn(v2 - f1.x, v3 - f1.y);
        }
    }
}

// ------------------- flash attention: K/V both [b][l][c], K via non-trans ldsm -------------------
// pool (halves): Q hi [0, 5120) (overlaid by buf1); buf1 = [0, 10240); buf0 = [10240, 20480)
// buffer layout: Kh +0, Kl +2560, Vh +5120, Vl +7680 (each 64 rows x pitch 40)
__global__ void __launch_bounds__(256, 2)
attn_mma_kernel()
{
    __shared__ __align__(16) __half pool[20480];

    const int tid = threadIdx.x, lane = tid & 31, w = tid >> 5;
    const int qt = blockIdx.x, n = blockIdx.y, b = blockIdx.z;
    const int rr = lane & 15;
    const int hoff = (lane & 16) ? 8 : 0;
    // non-trans B addressing for K: n-row / k-col halves
    const int knr = (lane & 7) + ((lane >> 4) << 3);
    const int knc = ((lane >> 3) & 1) * 8;

    const int kvrow = tid >> 2, kvseg = tid & 3;

    // prologue: t=0 K/V into buf0
    {
        __half* base = pool + 10240;
        size_t g = ((size_t)(b * 1024 + kvrow)) * C_DIM + n * 32 + kvseg * 8;
        uint32_t s = smem_u32(base + kvrow * 40 + kvseg * 8);
        cpa16(s, &g_kth[g]);
        cpa16(s + 2560 * 2, &g_ktl[g]);
        cpa16(s + 5120 * 2, &g_vth[g]);
        cpa16(s + 7680 * 2, &g_vtl[g]);
        CP_COMMIT();
    }

    // stage Q hi (128 rows x 32 c)
    for (int u = tid; u < 512; u += 256) {
        int row = u >> 2, seg = u & 3;
        size_t g = ((size_t)(b * 1024 + qt * 128 + row)) * C_DIM + n * 32 + seg * 8;
        *(uint4*)&pool[row * 40 + seg * 8] = *(const uint4*)&g_qh[g];
    }
    __syncthreads();

    uint32_t qf[2][4];
    #pragma unroll
    for (int kc = 0; kc < 2; kc++)
        ldsm_x4(qf[kc], smem_u32(&pool[(w * 16 + rr) * 40 + kc * 16 + hoff]));
    __syncthreads();   // Q consumed; buf1 overlay may be written

    float oacc[4][4] = {};
    float m0 = -1e30f, m1 = -1e30f, l0 = 0.0f, l1 = 0.0f;

    for (int t = 0; t < 16; t++) {
        CP_WAIT0();
        __syncthreads();

        if (t < 15) {
            __half* base = pool + (((t + 1) & 1) ? 0 : 10240);
            size_t g = ((size_t)(b * 1024 + (t + 1) * 64 + kvrow)) * C_DIM + n * 32 + kvseg * 8;
            uint32_t s = smem_u32(base + kvrow * 40 + kvseg * 8);
            cpa16(s, &g_kth[g]);
            cpa16(s + 2560 * 2, &g_ktl[g]);
            cpa16(s + 5120 * 2, &g_vth[g]);
            cpa16(s + 7680 * 2, &g_vtl[g]);
            CP_COMMIT();
        }

        __half* cur = pool + ((t & 1) ? 0 : 10240);
        __half* ksh0 = cur;
        __half* ksh1 = cur + 2560;
        __half* vsh0 = cur + 5120;
        __half* vsh1 = cur + 7680;

        // ---- S = QhKh + QhKl (K B-operand via non-trans x4: 2 n-tiles per load) ----
        float sacc[8][4];
        #pragma unroll
        for (int ntp = 0; ntp < 4; ntp++) {
            float* s0 = sacc[2 * ntp];
            float* s1 = sacc[2 * ntp + 1];
            s0[0] = s0[1] = s0[2] = s0[3] = 0.0f;
            s1[0] = s1[1] = s1[2] = s1[3] = 0.0f;
            #pragma unroll
            for (int kc = 0; kc < 2; kc++) {
                uint32_t off = (ntp * 16 + knr) * 40 + kc * 16 + knc;
                uint32_t kbh[4], kbl[4];
                ldsm_x4(kbh, smem_u32(&ksh0[off]));
                ldsm_x4(kbl, smem_u32(&ksh1[off]));
                mma16816(s0, qf[kc], kbh);
                mma16816(s1, qf[kc], kbh + 2);
                mma16816(s0, qf[kc], kbl);
                mma16816(s1, qf[kc], kbl + 2);
            }
        }

        // ---- online softmax ----
        float mt0 = -1e30f, mt1 = -1e30f;
        #pragma unroll
        for (int nt = 0; nt < 8; nt++) {
            mt0 = fmaxf(mt0, fmaxf(sacc[nt][0], sacc[nt][1]));
            mt1 = fmaxf(mt1, fmaxf(sacc[nt][2], sacc[nt][3]));
        }
        mt0 = fmaxf(mt0, shflx(mt0, 1)); mt0 = fmaxf(mt0, shflx(mt0, 2));
        mt1 = fmaxf(mt1, shflx(mt1, 1)); mt1 = fmaxf(mt1, shflx(mt1, 2));
        float nm0 = fmaxf(m0, mt0), nm1 = fmaxf(m1, mt1);
        float c0 = ex2f(m0 - nm0), c1 = ex2f(m1 - nm1);
        m0 = nm0; m1 = nm1;
        l0 *= c0; l1 *= c1;
        #pragma unroll
        for (int nt = 0; nt < 4; nt++) {
            oacc[nt][0] *= c0; oacc[nt][1] *= c0;
            oacc[nt][2] *= c1; oacc[nt][3] *= c1;
        }
        float rs0 = 0.0f, rs1 = 0.0f;
        #pragma unroll
        for (int nt = 0; nt < 8; nt++) {
            sacc[nt][0] = ex2f(sacc[nt][0] - m0);
            sacc[nt][1] = ex2f(sacc[nt][1] - m0);
            sacc[nt][2] = ex2f(sacc[nt][2] - m1);
            sacc[nt][3] = ex2f(sacc[nt][3] - m1);
            rs0 += sacc[nt][0] + sacc[nt][1];
            rs1 += sacc[nt][2] + sacc[nt][3];
        }
        rs0 += shflx(rs0, 1); rs0 += shflx(rs0, 2);
        rs1 += shflx(rs1, 1); rs1 += shflx(rs1, 2);
        l0 += rs0; l1 += rs1;

        // ---- P hi-only fragments ----
        uint32_t pfh[4][4];
        #pragma unroll
        for (int kc = 0; kc < 4; kc++) {
            const float* s0 = sacc[2 * kc];
            const float* s1 = sacc[2 * kc + 1];
            pfh[kc][0] = pack_h2(s0[0], s0[1]);
            pfh[kc][1] = pack_h2(s0[2], s0[3]);
            pfh[kc][2] = pack_h2(s1[0], s1[1]);
            pfh[kc][3] = pack_h2(s1[2], s1[3]);
        }

        // ---- O += Ph*Vh + Ph*Vl ----
        #pragma unroll
        for (int kc = 0; kc < 4; kc++) {
            #pragma unroll
            for (int np = 0; np < 2; np++) {
                uint32_t vbh[4], vbl[4];
                uint32_t off = (kc * 16 + rr) * 40 + np * 16 + hoff;
                ldsm_x4t(vbh, smem_u32(&vsh0[off]));
                ldsm_x4t(vbl, smem_u32(&vsh1[off]));
                mma16816(oacc[2 * np],     pfh[kc], vbh);
                mma16816(oacc[2 * np + 1], pfh[kc], vbh + 2);
                mma16816(oacc[2 * np],     pfh[kc], vbl);
                mma16816(oacc[2 * np + 1], pfh[kc], vbl + 2);
            }
        }
    }

    // ---- epilogue: O as f16 hi/lo split [b][c][l] ----
    float i0 = 1.0f / l0, i1 = 1.0f / l1;
    int q0 = qt * 128 + w * 16 + (lane >> 2);
    #pragma unroll
    for (int nt = 0; nt < 4; nt++) {
        int c = n * 32 + nt * 8 + (lane & 3) * 2;
        float v00 = oacc[nt][0] * i0, v01 = oacc[nt][1] * i0;
        float v10 = oacc[nt][2] * i1, v11 = oacc[nt][3] * i1;
        size_t b0 = ((size_t)(b * 256 + c)) * L_DIM + q0;
        size_t b1 = b0 + L_DIM;
        __half h;
        h = __float2half_rn(v00); g_xth[b0] = h;     g_xtl[b0] = __float2half_rn(v00 - __half2float(h));
        h = __float2half_rn(v01); g_xth[b1] = h;     g_xtl[b1] = __float2half_rn(v01 - __half2float(h));
        h = __float2half_rn(v10); g_xth[b0 + 8] = h; g_xtl[b0 + 8] = __float2half_rn(v10 - __half2float(h));
        h = __float2half_rn(v11); g_xth[b1 + 8] = h; g_xtl[b1 + 8] = __float2half_rn(v11 - __half2float(h));
    }
}

// ------------------- mma output projection: cp.async double-buffered -------------------
__global__ void __launch_bounds__(256)
proj_o_mma_kernel(const float* __restrict__ bo, float* __restrict__ out)
{
    extern __shared__ __half dynsm[];
    __shared__ float bias_s[128];

    const int tid = threadIdx.x, lane = tid & 31, w = tid >> 5;
    const int lt = blockIdx.x >> 1, oh = blockIdx.x & 1;
    const int b = blockIdx.z;

    if (tid < 128) bias_s[tid] = bo[oh * 128 + tid];

    const int arow = tid >> 2, aseg = tid & 3;
    const int brow = tid >> 4, bseg = tid & 15;

    {
        __half* base = dynsm;
        #pragma unroll
        for (int i = 0; i < 2; i++) {
            int row = arow + i * 64;
            int g = (oh * 128 + row) * C_DIM + aseg * 8;
            cpa16(smem_u32(base + row * 40 + aseg * 8), &g_woh[g]);
            cpa16(smem_u32(base + 5120 + row * 40 + aseg * 8), &g_wol[g]);
        }
        #pragma unroll
        for (int i = 0; i < 2; i++) {
            int row = brow + i * 16;
            size_t g = ((size_t)(b * 256 + row)) * L_DIM + lt * 128 + bseg * 8;
            cpa16(smem_u32(base + 10240 + row * 136 + bseg * 8), &g_xth[g]);
            cpa16(smem_u32(base + 14592 + row * 136 + bseg * 8), &g_xtl[g]);
        }
        CP_COMMIT();
    }

    float acc[16][4] = {};
    const int rr = lane & 15;
    const int chi = (lane & 16) ? 8 : 0;

    for (int it = 0; it < 8; it++) {
        CP_WAIT0();
        __syncthreads();

        if (it < 7) {
            __half* base = dynsm + ((it + 1) & 1) * PJ_STAGE;
            int kc0 = (it + 1) * 32;
            #pragma unroll
            for (int i = 0; i < 2; i++) {
                int row = arow + i * 64;
                int g = (oh * 128 + row) * C_DIM + kc0 + aseg * 8;
                cpa16(smem_u32(base + row * 40 + aseg * 8), &g_woh[g]);
                cpa16(smem_u32(base + 5120 + row * 40 + aseg * 8), &g_wol[g]);
            }
            #pragma unroll
            for (int i = 0; i < 2; i++) {
                int row = brow + i * 16;
                size_t g = ((size_t)(b * 256 + kc0 + row)) * L_DIM + lt * 128 + bseg * 8;
                cpa16(smem_u32(base + 10240 + row * 136 + bseg * 8), &g_xth[g]);
                cpa16(smem_u32(base + 14592 + row * 136 + bseg * 8), &g_xtl[g]);
            }
            CP_COMMIT();
        }

        __half* cur = dynsm + (it & 1) * PJ_STAGE;
        __half* ah = cur;
        __half* al = cur + 5120;
        __half* bh_s = cur + 10240;
        __half* bl_s = cur + 14592;

        uint32_t af[2][2][4];
        #pragma unroll
        for (int kc = 0; kc < 2; kc++) {
            ldsm_x4(af[0][kc], smem_u32(&ah[(w * 16 + rr) * 40 + kc * 16 + chi]));
            ldsm_x4(af[1][kc], smem_u32(&al[(w * 16 + rr) * 40 + kc * 16 + chi]));
        }

        #pragma unroll
        for (int nt = 0; nt < 16; nt += 2) {
            #pragma unroll
            for (int kc = 0; kc < 2; kc++) {
                uint32_t bh[4], bl[4];
                ldsm_x4t(bh, smem_u32(&bh_s[(kc * 16 + rr) * 136 + nt * 8 + chi]));
                ldsm_x4t(bl, smem_u32(&bl_s[(kc * 16 + rr) * 136 + nt * 8 + chi]));
                mma16816(acc[nt],     af[0][kc], bh);
                mma16816(acc[nt + 1], af[0][kc], bh + 2);
                mma16816(acc[nt],     af[0][kc], bl);
                mma16816(acc[nt + 1], af[0][kc], bl + 2);
                mma16816(acc[nt],     af[1][kc], bh);
                mma16816(acc[nt + 1], af[1][kc], bh + 2);
            }
        }
    }

    const int orow = oh * 128 + w * 16 + (lane >> 2);
    const float bb0 = bias_s[w * 16 + (lane >> 2)];
    const float bb1 = bias_s[w * 16 + (lane >> 2) + 8];
    #pragma unroll
    for (int nt = 0; nt < 16; nt++) {
        int lcol = lt * 128 + nt * 8 + (lane & 3) * 2;
        float2 y0, y1;
        y0.x = acc[nt][0] + bb0; y0.y = acc[nt][1] + bb0;
        y1.x = acc[nt][2] + bb1; y1.y = acc[nt][3] + bb1;
        *(float2*)&out[((size_t)(b * 256 + orow)) * L_DIM + lcol] = y0;
        *(float2*)&out[((size_t)(b * 256 + orow + 8)) * L_DIM + lcol] = y1;
    }
}

// ---------------------------------------------------------------------------
extern "C" void kernel_launch(void* const* d_in, const int* in_sizes, int n_in,
                              void* d_out, int out_size)
{
    const float* x  = (const float*)d_in[0];
    const float* wq = (const float*)d_in[1];
    const float* bq = (const float*)d_in[2];
    const float* wk = (const float*)d_in[3];
    const float* bk = (const float*)d_in[4];
    const float* wv = (const float*)d_in[5];
    const float* bv = (const float*)d_in[6];
    const float* wo = (const float*)d_in[7];
    const float* bo = (const float*)d_in[8];
    float* out = (float*)d_out;

    cudaFuncSetAttribute(proj_qkv_mma_kernel, cudaFuncAttributeMaxDynamicSharedMemorySize, PJ_BYTES);
    cudaFuncSetAttribute(proj_o_mma_kernel, cudaFuncAttributeMaxDynamicSharedMemorySize, PJ_BYTES);

    split_w_kernel<<<dim3(8, 8, 3), dim3(32, 8)>>>(wq, wk, wv);
    split_wo_kernel<<<128, 256>>>(wo);
    convert_x_kernel<<<dim3(32, 8, 16), dim3(32, 8)>>>(x);
    proj_qkv_mma_kernel<<<dim3(16, 3, 16), 256, PJ_BYTES>>>(bq, bk, bv);
    attn_mma_kernel<<<dim3(8, 8, 16), 256>>>();
    proj_o_mma_kernel<<<dim3(16, 1, 16), 256, PJ_BYTES>>>(bo, out);
}